// round 1
// baseline (speedup 1.0000x reference)
#include <cuda_runtime.h>
#include <math.h>

#define BDIM   1024
#define NHEAD  16
#define DHEAD  64
#define SEQ    2048
#define BATCH  2
#define NTOK   (BATCH * SEQ)      // 4096
#define HID    (4 * BDIM)         // 4096
#define EPSV   1e-6f

// ---------------- scratch (static device arrays; no runtime allocation) ----
__device__ float g_xn  [(size_t)NTOK * BDIM];       // 16 MB  rmsnorm output
__device__ float g_qkv [(size_t)NTOK * 3 * BDIM];   // 48 MB
__device__ float g_attn[(size_t)NTOK * BDIM];       // 16 MB  attention core out
__device__ float g_x1  [(size_t)NTOK * BDIM];       // 16 MB  residual after attn
__device__ float g_h   [(size_t)NTOK * HID];        // 64 MB  mlp hidden

// ---------------- rmsnorm --------------------------------------------------
__global__ void rmsnorm_kernel(const float* __restrict__ x,
                               const float* __restrict__ scale,
                               float* __restrict__ out)
{
    int row = blockIdx.x;                 // one block per token
    const float4* xr = (const float4*)(x + (size_t)row * BDIM);
    float4 v = xr[threadIdx.x];           // 256 threads * 4 = 1024
    float ss = v.x * v.x + v.y * v.y + v.z * v.z + v.w * v.w;
    #pragma unroll
    for (int o = 16; o > 0; o >>= 1) ss += __shfl_xor_sync(0xffffffffu, ss, o);
    __shared__ float ws[8];
    int w = threadIdx.x >> 5;
    if ((threadIdx.x & 31) == 0) ws[w] = ss;
    __syncthreads();
    float tot = ws[0] + ws[1] + ws[2] + ws[3] + ws[4] + ws[5] + ws[6] + ws[7];
    float inv = 1.0f / sqrtf(tot * (1.0f / BDIM) + EPSV);
    float4 sc = ((const float4*)scale)[threadIdx.x];
    float4 o4;
    o4.x = v.x * inv * sc.x;
    o4.y = v.y * inv * sc.y;
    o4.z = v.z * inv * sc.z;
    o4.w = v.w * inv * sc.w;
    ((float4*)(out + (size_t)row * BDIM))[threadIdx.x] = o4;
}

// ---------------- generic TN GEMM: C[M,N] = A[M,K] * B[N,K]^T --------------
// EPI: 0 = store, 1 = store + residual R, 2 = C *= silu(acc)  (RMW of C)
#define GBM 128
#define GBN 128
#define GBK 16
#define GPAD 4

template<int EPI>
__global__ __launch_bounds__(256, 2)
void gemm_tn(const float* __restrict__ A, const float* __restrict__ B,
             float* __restrict__ C, const float* __restrict__ R,
             int M, int N, int K)
{
    __shared__ float As[GBK][GBM + GPAD];
    __shared__ float Bs[GBK][GBN + GPAD];

    const int tid = threadIdx.x;
    const int tx = tid & 15, ty = tid >> 4;
    const int bm = blockIdx.y * GBM, bn = blockIdx.x * GBN;
    const float* Ab = A + (size_t)bm * K;
    const float* Bb = B + (size_t)bn * K;

    float acc[8][8];
    #pragma unroll
    for (int i = 0; i < 8; i++)
        #pragma unroll
        for (int j = 0; j < 8; j++) acc[i][j] = 0.0f;

    int lrow[2], lkc[2];
    #pragma unroll
    for (int i = 0; i < 2; i++) {
        int f = tid + i * 256;            // 0..511 float4 slots
        lrow[i] = f >> 2;                 // 0..127
        lkc[i]  = (f & 3) << 2;           // 0,4,8,12
    }

    float4 ra[2], rb[2];
    #pragma unroll
    for (int i = 0; i < 2; i++) {
        ra[i] = *(const float4*)(Ab + (size_t)lrow[i] * K + lkc[i]);
        rb[i] = *(const float4*)(Bb + (size_t)lrow[i] * K + lkc[i]);
    }

    for (int k0 = 0; k0 < K; k0 += GBK) {
        // commit current regs to smem (transposed to [k][mn])
        #pragma unroll
        for (int i = 0; i < 2; i++) {
            As[lkc[i] + 0][lrow[i]] = ra[i].x;
            As[lkc[i] + 1][lrow[i]] = ra[i].y;
            As[lkc[i] + 2][lrow[i]] = ra[i].z;
            As[lkc[i] + 3][lrow[i]] = ra[i].w;
            Bs[lkc[i] + 0][lrow[i]] = rb[i].x;
            Bs[lkc[i] + 1][lrow[i]] = rb[i].y;
            Bs[lkc[i] + 2][lrow[i]] = rb[i].z;
            Bs[lkc[i] + 3][lrow[i]] = rb[i].w;
        }
        __syncthreads();

        int k1 = k0 + GBK;
        if (k1 < K) {                     // prefetch next tile into regs
            #pragma unroll
            for (int i = 0; i < 2; i++) {
                ra[i] = *(const float4*)(Ab + (size_t)lrow[i] * K + k1 + lkc[i]);
                rb[i] = *(const float4*)(Bb + (size_t)lrow[i] * K + k1 + lkc[i]);
            }
        }

        #pragma unroll
        for (int kk = 0; kk < GBK; kk++) {
            float a[8], b[8];
            *(float4*)&a[0] = *(const float4*)&As[kk][ty * 8];
            *(float4*)&a[4] = *(const float4*)&As[kk][ty * 8 + 4];
            *(float4*)&b[0] = *(const float4*)&Bs[kk][tx * 8];
            *(float4*)&b[4] = *(const float4*)&Bs[kk][tx * 8 + 4];
            #pragma unroll
            for (int i = 0; i < 8; i++)
                #pragma unroll
                for (int j = 0; j < 8; j++)
                    acc[i][j] = fmaf(a[i], b[j], acc[i][j]);
        }
        __syncthreads();
    }

    // epilogue
    #pragma unroll
    for (int i = 0; i < 8; i++) {
        size_t base = (size_t)(bm + ty * 8 + i) * N + bn + tx * 8;
        #pragma unroll
        for (int j = 0; j < 8; j += 4) {
            float4 o;
            o.x = acc[i][j + 0]; o.y = acc[i][j + 1];
            o.z = acc[i][j + 2]; o.w = acc[i][j + 3];
            if (EPI == 1) {
                float4 r = *(const float4*)(R + base + j);
                o.x += r.x; o.y += r.y; o.z += r.z; o.w += r.w;
            } else if (EPI == 2) {
                float4 c = *(const float4*)(C + base + j);
                o.x = c.x * (o.x / (1.0f + expf(-o.x)));
                o.y = c.y * (o.y / (1.0f + expf(-o.y)));
                o.z = c.z * (o.z / (1.0f + expf(-o.z)));
                o.w = c.w * (o.w / (1.0f + expf(-o.w)));
            }
            *(float4*)(C + base + j) = o;
        }
    }
}

// ---------------- flash attention (fp32, causal, 64x64 tiles) --------------
// grid: (SEQ/64, NHEAD, BATCH), 256 threads. Dynamic smem:
//   Qs[64][64] | KsPs[64][65] (K tile, reused as P tile) | Vs[64][64]
#define ATT_SMEM_FLOATS (64 * 64 + 64 * 65 + 64 * 64)

__global__ __launch_bounds__(256, 2)
void flash_attn_kernel(const float* __restrict__ qkv, float* __restrict__ out)
{
    extern __shared__ float sm[];
    float* Qs = sm;                       // [64][64] row-major
    float* Ks = sm + 64 * 64;             // [64][65] (also Ps)
    float* Vs = Ks + 64 * 65;             // [64][64]

    const int qb = blockIdx.x, h = blockIdx.y, b = blockIdx.z;
    const int q0 = qb * 64;
    const int tid = threadIdx.x;
    const int tx = tid & 15, ty = tid >> 4;
    const int ld = 3 * BDIM;

    const float* qbase = qkv + ((size_t)(b * SEQ + q0)) * ld + h * DHEAD;
    #pragma unroll
    for (int i = 0; i < 4; i++) {
        int f = tid + i * 256;            // 1024 float4 slots
        int r = f >> 4, c4 = f & 15;
        float4 v = *(const float4*)(qbase + (size_t)r * ld + c4 * 4);
        *(float4*)(Qs + r * 64 + c4 * 4) = v;
    }

    float o[4][4];
    float mrow[4], lsum[4];
    #pragma unroll
    for (int i = 0; i < 4; i++) {
        mrow[i] = -3.0e38f; lsum[i] = 0.0f;
        #pragma unroll
        for (int j = 0; j < 4; j++) o[i][j] = 0.0f;
    }

    const float* kbase = qkv + (size_t)(b * SEQ) * ld + BDIM     + h * DHEAD;
    const float* vbase = qkv + (size_t)(b * SEQ) * ld + 2 * BDIM + h * DHEAD;

    const int ntiles = qb + 1;            // causal: skip tiles above diagonal
    for (int t = 0; t < ntiles; t++) {
        const int kv0 = t * 64;
        __syncthreads();                  // prev-phase readers done (also Q store)
        #pragma unroll
        for (int i = 0; i < 4; i++) {
            int f = tid + i * 256;
            int r = f >> 4, c4 = f & 15;
            float4 kvv = *(const float4*)(kbase + (size_t)(kv0 + r) * ld + c4 * 4);
            Ks[r * 65 + c4 * 4 + 0] = kvv.x;
            Ks[r * 65 + c4 * 4 + 1] = kvv.y;
            Ks[r * 65 + c4 * 4 + 2] = kvv.z;
            Ks[r * 65 + c4 * 4 + 3] = kvv.w;
            float4 vv = *(const float4*)(vbase + (size_t)(kv0 + r) * ld + c4 * 4);
            *(float4*)(Vs + r * 64 + c4 * 4) = vv;
        }
        __syncthreads();

        // S = Q K^T  (each thread: rows ty*4.., cols tx*4..)
        float s[4][4];
        #pragma unroll
        for (int i = 0; i < 4; i++)
            #pragma unroll
            for (int j = 0; j < 4; j++) s[i][j] = 0.0f;
        #pragma unroll 4
        for (int kd = 0; kd < 64; kd++) {
            float a[4], bb[4];
            #pragma unroll
            for (int i = 0; i < 4; i++) a[i]  = Qs[(ty * 4 + i) * 64 + kd];
            #pragma unroll
            for (int j = 0; j < 4; j++) bb[j] = Ks[(tx * 4 + j) * 65 + kd];
            #pragma unroll
            for (int i = 0; i < 4; i++)
                #pragma unroll
                for (int j = 0; j < 4; j++)
                    s[i][j] = fmaf(a[i], bb[j], s[i][j]);
        }

        const float scale = 0.125f;       // 1/sqrt(64)
        if (t == ntiles - 1) {            // diagonal tile: mask kv > q
            #pragma unroll
            for (int i = 0; i < 4; i++)
                #pragma unroll
                for (int j = 0; j < 4; j++)
                    s[i][j] = (tx * 4 + j > ty * 4 + i) ? -3.0e38f : s[i][j] * scale;
        } else {
            #pragma unroll
            for (int i = 0; i < 4; i++)
                #pragma unroll
                for (int j = 0; j < 4; j++) s[i][j] *= scale;
        }

        // online softmax update (reduce across the 16-lane tx group)
        #pragma unroll
        for (int i = 0; i < 4; i++) {
            float mx = fmaxf(fmaxf(s[i][0], s[i][1]), fmaxf(s[i][2], s[i][3]));
            #pragma unroll
            for (int od = 8; od > 0; od >>= 1)
                mx = fmaxf(mx, __shfl_xor_sync(0xffffffffu, mx, od));
            float mnew = fmaxf(mrow[i], mx);
            float fac = __expf(mrow[i] - mnew);
            float ps = 0.0f;
            #pragma unroll
            for (int j = 0; j < 4; j++) {
                s[i][j] = __expf(s[i][j] - mnew);
                ps += s[i][j];
            }
            #pragma unroll
            for (int od = 8; od > 0; od >>= 1)
                ps += __shfl_xor_sync(0xffffffffu, ps, od);
            lsum[i] = lsum[i] * fac + ps;
            mrow[i] = mnew;
            #pragma unroll
            for (int j = 0; j < 4; j++) o[i][j] *= fac;
        }

        __syncthreads();                  // all Ks reads done; reuse as Ps
        float* Ps = Ks;
        #pragma unroll
        for (int i = 0; i < 4; i++)
            #pragma unroll
            for (int j = 0; j < 4; j++)
                Ps[(ty * 4 + i) * 65 + tx * 4 + j] = s[i][j];
        __syncthreads();

        // O += P V  (each thread: rows ty*4.., dh cols tx*4..)
        #pragma unroll 4
        for (int kv = 0; kv < 64; kv++) {
            float p[4], vv[4];
            #pragma unroll
            for (int i = 0; i < 4; i++) p[i] = Ps[(ty * 4 + i) * 65 + kv];
            *(float4*)&vv[0] = *(const float4*)(Vs + kv * 64 + tx * 4);
            #pragma unroll
            for (int i = 0; i < 4; i++)
                #pragma unroll
                for (int j = 0; j < 4; j++)
                    o[i][j] = fmaf(p[i], vv[j], o[i][j]);
        }
    }

    #pragma unroll
    for (int i = 0; i < 4; i++) {
        float invl = 1.0f / lsum[i];
        int r = q0 + ty * 4 + i;
        float4 o4;
        o4.x = o[i][0] * invl; o4.y = o[i][1] * invl;
        o4.z = o[i][2] * invl; o4.w = o[i][3] * invl;
        *(float4*)(out + ((size_t)(b * SEQ) + r) * BDIM + h * DHEAD + tx * 4) = o4;
    }
}

// ---------------- launch ---------------------------------------------------
extern "C" void kernel_launch(void* const* d_in, const int* in_sizes, int n_in,
                              void* d_out, int out_size)
{
    const float* x      = (const float*)d_in[0];
    const float* w_qkv  = (const float*)d_in[1];
    const float* w_o    = (const float*)d_in[2];
    const float* w_up   = (const float*)d_in[3];
    const float* w_gate = (const float*)d_in[4];
    const float* w_down = (const float*)d_in[5];
    const float* scale1 = (const float*)d_in[6];
    const float* scale2 = (const float*)d_in[7];
    float* out = (float*)d_out;

    float *xn, *qkvb, *attn, *x1, *hbuf;
    cudaGetSymbolAddress((void**)&xn,   g_xn);
    cudaGetSymbolAddress((void**)&qkvb, g_qkv);
    cudaGetSymbolAddress((void**)&attn, g_attn);
    cudaGetSymbolAddress((void**)&x1,   g_x1);
    cudaGetSymbolAddress((void**)&hbuf, g_h);

    const int att_smem = ATT_SMEM_FLOATS * (int)sizeof(float);
    cudaFuncSetAttribute(flash_attn_kernel,
                         cudaFuncAttributeMaxDynamicSharedMemorySize, att_smem);

    // 1. rmsnorm(x, scale1) -> xn
    rmsnorm_kernel<<<NTOK, 256>>>(x, scale1, xn);

    // 2. qkv = xn @ w_qkv.T
    {
        dim3 g(3 * BDIM / GBN, NTOK / GBM);
        gemm_tn<0><<<g, 256>>>(xn, w_qkv, qkvb, nullptr, NTOK, 3 * BDIM, BDIM);
    }

    // 3. attention core -> attn
    {
        dim3 g(SEQ / 64, NHEAD, BATCH);
        flash_attn_kernel<<<g, 256, att_smem>>>(qkvb, attn);
    }

    // 4. x1 = x + attn @ w_o.T
    {
        dim3 g(BDIM / GBN, NTOK / GBM);
        gemm_tn<1><<<g, 256>>>(attn, w_o, x1, x, NTOK, BDIM, BDIM);
    }

    // 5. rmsnorm(x1, scale2) -> xn
    rmsnorm_kernel<<<NTOK, 256>>>(x1, scale2, xn);

    // 6. h = xn @ w_up.T ;  7. h *= silu(xn @ w_gate.T)
    {
        dim3 g(HID / GBN, NTOK / GBM);
        gemm_tn<0><<<g, 256>>>(xn, w_up,   hbuf, nullptr, NTOK, HID, BDIM);
        gemm_tn<2><<<g, 256>>>(xn, w_gate, hbuf, nullptr, NTOK, HID, BDIM);
    }

    // 8. out = x1 + h @ w_down.T
    {
        dim3 g(BDIM / GBN, NTOK / GBM);
        gemm_tn<1><<<g, 256>>>(hbuf, w_down, out, x1, NTOK, BDIM, HID);
    }
}

// round 3
// speedup vs baseline: 1.7138x; 1.7138x over previous
#include <cuda_runtime.h>
#include <cuda_bf16.h>
#include <cstdint>
#include <math.h>

#define BDIM   1024
#define NHEAD  16
#define DHEAD  64
#define SEQ    2048
#define BATCH  2
#define NTOK   (BATCH * SEQ)      // 4096
#define HID    (4 * BDIM)         // 4096
#define EPSV   1e-6f

typedef __nv_bfloat16 bf;

// ===================== helpers =============================================
__device__ __forceinline__ uint32_t smem_u32(const void* p) {
    uint32_t a;
    asm("{ .reg .u64 t; cvta.to.shared.u64 t, %1; cvt.u32.u64 %0, t; }"
        : "=r"(a) : "l"(p));
    return a;
}

#define CP_ASYNC16(s, g) \
    asm volatile("cp.async.cg.shared.global [%0], [%1], 16;" :: "r"(s), "l"(g))
#define CP_COMMIT() asm volatile("cp.async.commit_group;" ::: "memory")
#define CP_WAIT2()  asm volatile("cp.async.wait_group 2;" ::: "memory")

#define LDSM4(r, a) \
    asm volatile("ldmatrix.sync.aligned.m8n8.x4.shared.b16 {%0,%1,%2,%3}, [%4];" \
        : "=r"((r)[0]), "=r"((r)[1]), "=r"((r)[2]), "=r"((r)[3]) : "r"(a))

#define MMA16816(d, a, b0, b1) \
    asm volatile("mma.sync.aligned.m16n8k16.row.col.f32.bf16.bf16.f32 " \
        "{%0,%1,%2,%3}, {%4,%5,%6,%7}, {%8,%9}, {%0,%1,%2,%3};" \
        : "+f"((d)[0]), "+f"((d)[1]), "+f"((d)[2]), "+f"((d)[3]) \
        : "r"((a)[0]), "r"((a)[1]), "r"((a)[2]), "r"((a)[3]), "r"(b0), "r"(b1))

__device__ __forceinline__ void f2hilo(float v, bf& h, bf& l) {
    h = __float2bfloat16(v);
    l = __float2bfloat16(v - __bfloat162float(h));
}

// ===================== scratch ==============================================
__device__ float g_qkv[(size_t)NTOK * 3 * BDIM];
__device__ float g_x1 [(size_t)NTOK * BDIM];
__device__ float g_h  [(size_t)NTOK * HID];
__device__ unsigned short g_xnh[(size_t)NTOK * BDIM], g_xnl[(size_t)NTOK * BDIM];
__device__ unsigned short g_ath[(size_t)NTOK * BDIM], g_atl[(size_t)NTOK * BDIM];
__device__ unsigned short g_hh [(size_t)NTOK * HID],  g_hl [(size_t)NTOK * HID];
__device__ unsigned short g_wqkvh[(size_t)3 * BDIM * BDIM], g_wqkvl[(size_t)3 * BDIM * BDIM];
__device__ unsigned short g_woh[(size_t)BDIM * BDIM],  g_wol[(size_t)BDIM * BDIM];
__device__ unsigned short g_wuph[(size_t)HID * BDIM],  g_wupl[(size_t)HID * BDIM];
__device__ unsigned short g_wgh [(size_t)HID * BDIM],  g_wgl [(size_t)HID * BDIM];
__device__ unsigned short g_wdh [(size_t)BDIM * HID],  g_wdl [(size_t)BDIM * HID];

// ===================== convert fp32 -> bf16 hi/lo ===========================
__global__ void cvt_hilo(const float* __restrict__ in,
                         bf* __restrict__ hi, bf* __restrict__ lo, int n)
{
    int i4 = (blockIdx.x * blockDim.x + threadIdx.x) * 4;
    if (i4 >= n) return;
    float4 v = *(const float4*)(in + i4);
    bf h0, h1, h2, h3, l0, l1, l2, l3;
    f2hilo(v.x, h0, l0); f2hilo(v.y, h1, l1);
    f2hilo(v.z, h2, l2); f2hilo(v.w, h3, l3);
    *(__nv_bfloat162*)(hi + i4)     = __halves2bfloat162(h0, h1);
    *(__nv_bfloat162*)(hi + i4 + 2) = __halves2bfloat162(h2, h3);
    *(__nv_bfloat162*)(lo + i4)     = __halves2bfloat162(l0, l1);
    *(__nv_bfloat162*)(lo + i4 + 2) = __halves2bfloat162(l2, l3);
}

// ===================== rmsnorm -> bf16 hi/lo ================================
__global__ void rmsnorm_hilo(const float* __restrict__ x,
                             const float* __restrict__ scale,
                             bf* __restrict__ ohi, bf* __restrict__ olo)
{
    int row = blockIdx.x;
    float4 v = ((const float4*)(x + (size_t)row * BDIM))[threadIdx.x];
    float ss = v.x * v.x + v.y * v.y + v.z * v.z + v.w * v.w;
    #pragma unroll
    for (int o = 16; o > 0; o >>= 1) ss += __shfl_xor_sync(0xffffffffu, ss, o);
    __shared__ float ws[8];
    if ((threadIdx.x & 31) == 0) ws[threadIdx.x >> 5] = ss;
    __syncthreads();
    float tot = ws[0] + ws[1] + ws[2] + ws[3] + ws[4] + ws[5] + ws[6] + ws[7];
    float inv = 1.0f / sqrtf(tot * (1.0f / BDIM) + EPSV);
    float4 sc = ((const float4*)scale)[threadIdx.x];
    float o0 = v.x * inv * sc.x, o1 = v.y * inv * sc.y;
    float o2 = v.z * inv * sc.z, o3 = v.w * inv * sc.w;
    bf h0, h1, h2, h3, l0, l1, l2, l3;
    f2hilo(o0, h0, l0); f2hilo(o1, h1, l1); f2hilo(o2, h2, l2); f2hilo(o3, h3, l3);
    size_t off = (size_t)row * BDIM + threadIdx.x * 4;
    *(__nv_bfloat162*)(ohi + off)     = __halves2bfloat162(h0, h1);
    *(__nv_bfloat162*)(ohi + off + 2) = __halves2bfloat162(h2, h3);
    *(__nv_bfloat162*)(olo + off)     = __halves2bfloat162(l0, l1);
    *(__nv_bfloat162*)(olo + off + 2) = __halves2bfloat162(l2, l3);
}

// ===================== HMMA bf16x3 GEMM =====================================
// C[M,N] = A[M,K] * B[N,K]^T with A,B as bf16 hi/lo pairs; fp32 accum.
// EPI 0: C = acc
// EPI 1: C = acc + R
// EPI 2: v = C * silu(acc); write v as bf16 hi/lo to O1/O2
#define BM 128
#define BN 128
#define BKE 32                      // bf16 elems per k-chunk
#define LDSB 80                     // padded row stride in bytes (32*2 + 16)
#define BUF_B (BM * LDSB)           // 10240 bytes per buffer
#define STG_B (4 * BUF_B)           // Ahi|Alo|Bhi|Blo = 40960 bytes per stage
#define NSTAGE 3
#define GEMM_SMEM (NSTAGE * STG_B)  // 122880

template<int EPI>
__global__ __launch_bounds__(256, 1)
void gemm_hmma(const bf* __restrict__ Ahi, const bf* __restrict__ Alo,
               const bf* __restrict__ Bhi, const bf* __restrict__ Blo,
               float* __restrict__ C, const float* __restrict__ R,
               bf* __restrict__ O1, bf* __restrict__ O2,
               int M, int N, int K)
{
    extern __shared__ char smem[];
    const uint32_t sb = smem_u32(smem);

    const int tid  = threadIdx.x;
    const int lane = tid & 31;
    const int wid  = tid >> 5;
    const int wm   = wid & 3;        // 4 warps along M
    const int wn   = wid >> 2;       // 2 warps along N
    const int bm = blockIdx.y * BM, bn = blockIdx.x * BN;

    // ---- global->shared load slots: per buffer, 2 x 16B chunks per thread
    const bf* gptr[4][2];
    uint32_t  sptr[4][2];
    {
        const bf* gsrc[4] = {Ahi, Alo, Bhi, Blo};
        #pragma unroll
        for (int q = 0; q < 4; q++) {
            int rbase = (q < 2) ? bm : bn;
            #pragma unroll
            for (int j = 0; j < 2; j++) {
                int idx = tid * 2 + j;         // 0..511
                int row = idx >> 2, kc = idx & 3;
                gptr[q][j] = gsrc[q] + (size_t)(rbase + row) * K + kc * 8;
                sptr[q][j] = sb + q * BUF_B + row * LDSB + kc * 16;
            }
        }
    }

    const int nch = K / BKE;

    // prologue: fill NSTAGE stages
    #pragma unroll
    for (int s = 0; s < NSTAGE; s++) {
        #pragma unroll
        for (int q = 0; q < 4; q++)
            #pragma unroll
            for (int j = 0; j < 2; j++)
                CP_ASYNC16(sptr[q][j] + s * STG_B, gptr[q][j] + s * BKE);
        CP_COMMIT();
    }

    // ---- ldmatrix lane addressing
    const int a_row = lane & 15;
    const int a_k   = (lane >> 4) * 8;
    const uint32_t pA = sb + (wm * 32 + a_row) * LDSB + a_k * 2;
    const int b_n = (lane & 7) + ((lane >> 4) & 1) * 8;
    const int b_k = ((lane >> 3) & 1) * 8;
    const uint32_t pB = sb + 2 * BUF_B + (wn * 64 + b_n) * LDSB + b_k * 2;

    float acc[2][8][4];
    #pragma unroll
    for (int i = 0; i < 2; i++)
        #pragma unroll
        for (int j = 0; j < 8; j++)
            #pragma unroll
            for (int r = 0; r < 4; r++) acc[i][j][r] = 0.0f;

    for (int c = 0; c < nch; c++) {
        CP_WAIT2();
        __syncthreads();
        const uint32_t so = (c % NSTAGE) * STG_B;

        #pragma unroll
        for (int ks = 0; ks < 2; ks++) {
            uint32_t ah[2][4], al[2][4], bh[4][4], bl[4][4];
            #pragma unroll
            for (int i = 0; i < 2; i++) {
                LDSM4(ah[i], pA + so + i * (16 * LDSB) + ks * 32);
                LDSM4(al[i], pA + so + i * (16 * LDSB) + ks * 32 + BUF_B);
            }
            #pragma unroll
            for (int j2 = 0; j2 < 4; j2++) {
                LDSM4(bh[j2], pB + so + j2 * (16 * LDSB) + ks * 32);
                LDSM4(bl[j2], pB + so + j2 * (16 * LDSB) + ks * 32 + BUF_B);
            }
            #pragma unroll
            for (int i = 0; i < 2; i++)
                #pragma unroll
                for (int j = 0; j < 8; j++) {
                    const int j2 = j >> 1, hh = (j & 1) * 2;
                    MMA16816(acc[i][j], ah[i], bh[j2][hh], bh[j2][hh + 1]);
                    MMA16816(acc[i][j], ah[i], bl[j2][hh], bl[j2][hh + 1]);
                    MMA16816(acc[i][j], al[i], bh[j2][hh], bh[j2][hh + 1]);
                }
        }
        __syncthreads();

        const int cn = c + NSTAGE;
        if (cn < nch) {
            #pragma unroll
            for (int q = 0; q < 4; q++)
                #pragma unroll
                for (int j = 0; j < 2; j++)
                    CP_ASYNC16(sptr[q][j] + so, gptr[q][j] + cn * BKE);
            CP_COMMIT();
        }
    }

    // ---- epilogue
    const int g  = lane >> 2;
    const int c2 = (lane & 3) * 2;
    #pragma unroll
    for (int i = 0; i < 2; i++) {
        #pragma unroll
        for (int j = 0; j < 8; j++) {
            const int col = bn + wn * 64 + j * 8 + c2;
            const int r0 = bm + wm * 32 + i * 16 + g;
            #pragma unroll
            for (int hrow = 0; hrow < 2; hrow++) {
                const int row = r0 + hrow * 8;
                const size_t base = (size_t)row * N + col;
                float v0 = acc[i][j][hrow * 2 + 0];
                float v1 = acc[i][j][hrow * 2 + 1];
                if (EPI == 0) {
                    *(float2*)(C + base) = make_float2(v0, v1);
                } else if (EPI == 1) {
                    float2 rv = *(const float2*)(R + base);
                    *(float2*)(C + base) = make_float2(v0 + rv.x, v1 + rv.y);
                } else {
                    float2 u = *(const float2*)(C + base);
                    float s0 = u.x * (v0 / (1.0f + __expf(-v0)));
                    float s1 = u.y * (v1 / (1.0f + __expf(-v1)));
                    bf h0, h1, l0, l1;
                    f2hilo(s0, h0, l0); f2hilo(s1, h1, l1);
                    *(__nv_bfloat162*)(O1 + base) = __halves2bfloat162(h0, h1);
                    *(__nv_bfloat162*)(O2 + base) = __halves2bfloat162(l0, l1);
                }
            }
        }
    }
}

// ===================== flash attention (fp32, causal) -> bf16 hi/lo ========
#define ATT_SMEM_FLOATS (64 * 64 + 64 * 65 + 64 * 64)

__global__ __launch_bounds__(256, 2)
void flash_attn_kernel(const float* __restrict__ qkv,
                       bf* __restrict__ ahi, bf* __restrict__ alo2)
{
    extern __shared__ float sm[];
    float* Qs = sm;
    float* Ks = sm + 64 * 64;
    float* Vs = Ks + 64 * 65;

    const int qb = blockIdx.x, hd = blockIdx.y, b = blockIdx.z;
    const int q0 = qb * 64;
    const int tid = threadIdx.x;
    const int tx = tid & 15, ty = tid >> 4;
    const int ld = 3 * BDIM;

    const float* qbase = qkv + ((size_t)(b * SEQ + q0)) * ld + hd * DHEAD;
    #pragma unroll
    for (int i = 0; i < 4; i++) {
        int f = tid + i * 256;
        int r = f >> 4, c4 = f & 15;
        *(float4*)(Qs + r * 64 + c4 * 4) = *(const float4*)(qbase + (size_t)r * ld + c4 * 4);
    }

    float o[4][4], mrow[4], lsum[4];
    #pragma unroll
    for (int i = 0; i < 4; i++) {
        mrow[i] = -3.0e38f; lsum[i] = 0.0f;
        #pragma unroll
        for (int j = 0; j < 4; j++) o[i][j] = 0.0f;
    }

    const float* kbase = qkv + (size_t)(b * SEQ) * ld + BDIM     + hd * DHEAD;
    const float* vbase = qkv + (size_t)(b * SEQ) * ld + 2 * BDIM + hd * DHEAD;

    const int ntiles = qb + 1;
    for (int t = 0; t < ntiles; t++) {
        const int kv0 = t * 64;
        __syncthreads();
        #pragma unroll
        for (int i = 0; i < 4; i++) {
            int f = tid + i * 256;
            int r = f >> 4, c4 = f & 15;
            float4 kvv = *(const float4*)(kbase + (size_t)(kv0 + r) * ld + c4 * 4);
            Ks[r * 65 + c4 * 4 + 0] = kvv.x;
            Ks[r * 65 + c4 * 4 + 1] = kvv.y;
            Ks[r * 65 + c4 * 4 + 2] = kvv.z;
            Ks[r * 65 + c4 * 4 + 3] = kvv.w;
            *(float4*)(Vs + r * 64 + c4 * 4) = *(const float4*)(vbase + (size_t)(kv0 + r) * ld + c4 * 4);
        }
        __syncthreads();

        float s[4][4];
        #pragma unroll
        for (int i = 0; i < 4; i++)
            #pragma unroll
            for (int j = 0; j < 4; j++) s[i][j] = 0.0f;
        #pragma unroll 4
        for (int kd = 0; kd < 64; kd++) {
            float a[4], bb[4];
            #pragma unroll
            for (int i = 0; i < 4; i++) a[i]  = Qs[(ty * 4 + i) * 64 + kd];
            #pragma unroll
            for (int j = 0; j < 4; j++) bb[j] = Ks[(tx * 4 + j) * 65 + kd];
            #pragma unroll
            for (int i = 0; i < 4; i++)
                #pragma unroll
                for (int j = 0; j < 4; j++) s[i][j] = fmaf(a[i], bb[j], s[i][j]);
        }

        const float scale = 0.125f;
        if (t == ntiles - 1) {
            #pragma unroll
            for (int i = 0; i < 4; i++)
                #pragma unroll
                for (int j = 0; j < 4; j++)
                    s[i][j] = (tx * 4 + j > ty * 4 + i) ? -3.0e38f : s[i][j] * scale;
        } else {
            #pragma unroll
            for (int i = 0; i < 4; i++)
                #pragma unroll
                for (int j = 0; j < 4; j++) s[i][j] *= scale;
        }

        #pragma unroll
        for (int i = 0; i < 4; i++) {
            float mx = fmaxf(fmaxf(s[i][0], s[i][1]), fmaxf(s[i][2], s[i][3]));
            #pragma unroll
            for (int od = 8; od > 0; od >>= 1)
                mx = fmaxf(mx, __shfl_xor_sync(0xffffffffu, mx, od));
            float mnew = fmaxf(mrow[i], mx);
            float fac = __expf(mrow[i] - mnew);
            float ps = 0.0f;
            #pragma unroll
            for (int j = 0; j < 4; j++) { s[i][j] = __expf(s[i][j] - mnew); ps += s[i][j]; }
            #pragma unroll
            for (int od = 8; od > 0; od >>= 1)
                ps += __shfl_xor_sync(0xffffffffu, ps, od);
            lsum[i] = lsum[i] * fac + ps;
            mrow[i] = mnew;
            #pragma unroll
            for (int j = 0; j < 4; j++) o[i][j] *= fac;
        }

        __syncthreads();
        float* Ps = Ks;
        #pragma unroll
        for (int i = 0; i < 4; i++)
            #pragma unroll
            for (int j = 0; j < 4; j++)
                Ps[(ty * 4 + i) * 65 + tx * 4 + j] = s[i][j];
        __syncthreads();

        #pragma unroll 4
        for (int kv = 0; kv < 64; kv++) {
            float p[4], vv[4];
            #pragma unroll
            for (int i = 0; i < 4; i++) p[i] = Ps[(ty * 4 + i) * 65 + kv];
            *(float4*)&vv[0] = *(const float4*)(Vs + kv * 64 + tx * 4);
            #pragma unroll
            for (int i = 0; i < 4; i++)
                #pragma unroll
                for (int j = 0; j < 4; j++) o[i][j] = fmaf(p[i], vv[j], o[i][j]);
        }
    }

    #pragma unroll
    for (int i = 0; i < 4; i++) {
        float invl = 1.0f / lsum[i];
        int r = q0 + ty * 4 + i;
        bf h[4], l[4];
        #pragma unroll
        for (int j = 0; j < 4; j++) f2hilo(o[i][j] * invl, h[j], l[j]);
        size_t off = ((size_t)(b * SEQ) + r) * BDIM + hd * DHEAD + tx * 4;
        *(__nv_bfloat162*)(ahi + off)      = __halves2bfloat162(h[0], h[1]);
        *(__nv_bfloat162*)(ahi + off + 2)  = __halves2bfloat162(h[2], h[3]);
        *(__nv_bfloat162*)(alo2 + off)     = __halves2bfloat162(l[0], l[1]);
        *(__nv_bfloat162*)(alo2 + off + 2) = __halves2bfloat162(l[2], l[3]);
    }
}

// ===================== launch ==============================================
extern "C" void kernel_launch(void* const* d_in, const int* in_sizes, int n_in,
                              void* d_out, int out_size)
{
    const float* x      = (const float*)d_in[0];
    const float* w_qkv  = (const float*)d_in[1];
    const float* w_o    = (const float*)d_in[2];
    const float* w_up   = (const float*)d_in[3];
    const float* w_gate = (const float*)d_in[4];
    const float* w_down = (const float*)d_in[5];
    const float* scale1 = (const float*)d_in[6];
    const float* scale2 = (const float*)d_in[7];
    float* out = (float*)d_out;

    float *qkvb, *x1, *hbuf;
    bf *xnh, *xnl, *ath, *atl, *hh, *hl;
    bf *wqkvh, *wqkvl, *woh, *wol, *wuph, *wupl, *wgh, *wgl, *wdh, *wdl;
    cudaGetSymbolAddress((void**)&qkvb, g_qkv);
    cudaGetSymbolAddress((void**)&x1,   g_x1);
    cudaGetSymbolAddress((void**)&hbuf, g_h);
    cudaGetSymbolAddress((void**)&xnh, g_xnh);  cudaGetSymbolAddress((void**)&xnl, g_xnl);
    cudaGetSymbolAddress((void**)&ath, g_ath);  cudaGetSymbolAddress((void**)&atl, g_atl);
    cudaGetSymbolAddress((void**)&hh,  g_hh);   cudaGetSymbolAddress((void**)&hl,  g_hl);
    cudaGetSymbolAddress((void**)&wqkvh, g_wqkvh); cudaGetSymbolAddress((void**)&wqkvl, g_wqkvl);
    cudaGetSymbolAddress((void**)&woh, g_woh);  cudaGetSymbolAddress((void**)&wol, g_wol);
    cudaGetSymbolAddress((void**)&wuph, g_wuph); cudaGetSymbolAddress((void**)&wupl, g_wupl);
    cudaGetSymbolAddress((void**)&wgh, g_wgh);  cudaGetSymbolAddress((void**)&wgl, g_wgl);
    cudaGetSymbolAddress((void**)&wdh, g_wdh);  cudaGetSymbolAddress((void**)&wdl, g_wdl);

    const int att_smem = ATT_SMEM_FLOATS * (int)sizeof(float);
    cudaFuncSetAttribute(flash_attn_kernel,
                         cudaFuncAttributeMaxDynamicSharedMemorySize, att_smem);
    cudaFuncSetAttribute(gemm_hmma<0>,
                         cudaFuncAttributeMaxDynamicSharedMemorySize, GEMM_SMEM);
    cudaFuncSetAttribute(gemm_hmma<1>,
                         cudaFuncAttributeMaxDynamicSharedMemorySize, GEMM_SMEM);
    cudaFuncSetAttribute(gemm_hmma<2>,
                         cudaFuncAttributeMaxDynamicSharedMemorySize, GEMM_SMEM);

    // weight conversion (hi/lo bf16)
    {
        int n;
        n = 3 * BDIM * BDIM; cvt_hilo<<<(n/4 + 255)/256, 256>>>(w_qkv,  wqkvh, wqkvl, n);
        n = BDIM * BDIM;     cvt_hilo<<<(n/4 + 255)/256, 256>>>(w_o,    woh,   wol,   n);
        n = HID * BDIM;      cvt_hilo<<<(n/4 + 255)/256, 256>>>(w_up,   wuph,  wupl,  n);
        n = HID * BDIM;      cvt_hilo<<<(n/4 + 255)/256, 256>>>(w_gate, wgh,   wgl,   n);
        n = BDIM * HID;      cvt_hilo<<<(n/4 + 255)/256, 256>>>(w_down, wdh,   wdl,   n);
    }

    // 1. xn = rmsnorm(x, scale1)  (bf16 hi/lo)
    rmsnorm_hilo<<<NTOK, 256>>>(x, scale1, xnh, xnl);

    // 2. qkv = xn @ w_qkv.T  (fp32)
    {
        dim3 g(3 * BDIM / BN, NTOK / BM);
        gemm_hmma<0><<<g, 256, GEMM_SMEM>>>(xnh, xnl, wqkvh, wqkvl,
                                            qkvb, nullptr, nullptr, nullptr,
                                            NTOK, 3 * BDIM, BDIM);
    }

    // 3. attention core -> attn (bf16 hi/lo)
    {
        dim3 g(SEQ / 64, NHEAD, BATCH);
        flash_attn_kernel<<<g, 256, att_smem>>>(qkvb, ath, atl);
    }

    // 4. x1 = x + attn @ w_o.T
    {
        dim3 g(BDIM / BN, NTOK / BM);
        gemm_hmma<1><<<g, 256, GEMM_SMEM>>>(ath, atl, woh, wol,
                                            x1, x, nullptr, nullptr,
                                            NTOK, BDIM, BDIM);
    }

    // 5. xn = rmsnorm(x1, scale2)
    rmsnorm_hilo<<<NTOK, 256>>>(x1, scale2, xnh, xnl);

    // 6. h = xn @ w_up.T (fp32); 7. h = h * silu(xn @ w_gate.T) -> bf16 hi/lo
    {
        dim3 g(HID / BN, NTOK / BM);
        gemm_hmma<0><<<g, 256, GEMM_SMEM>>>(xnh, xnl, wuph, wupl,
                                            hbuf, nullptr, nullptr, nullptr,
                                            NTOK, HID, BDIM);
        gemm_hmma<2><<<g, 256, GEMM_SMEM>>>(xnh, xnl, wgh, wgl,
                                            hbuf, nullptr, hh, hl,
                                            NTOK, HID, BDIM);
    }

    // 8. out = x1 + h @ w_down.T
    {
        dim3 g(BDIM / BN, NTOK / BM);
        gemm_hmma<1><<<g, 256, GEMM_SMEM>>>(hh, hl, wdh, wdl,
                                            out, x1, nullptr, nullptr,
                                            NTOK, BDIM, HID);
    }
}

// round 4
// speedup vs baseline: 2.2746x; 1.3272x over previous
#include <cuda_runtime.h>
#include <cuda_fp16.h>
#include <cstdint>
#include <math.h>

#define BDIM   1024
#define NHEAD  16
#define DHEAD  64
#define SEQ    2048
#define BATCH  2
#define NTOK   (BATCH * SEQ)      // 4096
#define HID    (4 * BDIM)         // 4096
#define EPSV   1e-6f

// ===================== helpers =============================================
__device__ __forceinline__ uint32_t smem_u32(const void* p) {
    uint32_t a;
    asm("{ .reg .u64 t; cvta.to.shared.u64 t, %1; cvt.u32.u64 %0, t; }"
        : "=r"(a) : "l"(p));
    return a;
}

#define CP_ASYNC16(s, g) \
    asm volatile("cp.async.cg.shared.global [%0], [%1], 16;" :: "r"(s), "l"(g))
#define CP_COMMIT() asm volatile("cp.async.commit_group;" ::: "memory")
#define CP_WAIT3()  asm volatile("cp.async.wait_group 3;" ::: "memory")

#define LDSM4(r, a) \
    asm volatile("ldmatrix.sync.aligned.m8n8.x4.shared.b16 {%0,%1,%2,%3}, [%4];" \
        : "=r"((r)[0]), "=r"((r)[1]), "=r"((r)[2]), "=r"((r)[3]) : "r"(a))

#define MMA16816(d, a, b0, b1) \
    asm volatile("mma.sync.aligned.m16n8k16.row.col.f32.f16.f16.f32 " \
        "{%0,%1,%2,%3}, {%4,%5,%6,%7}, {%8,%9}, {%0,%1,%2,%3};" \
        : "+f"((d)[0]), "+f"((d)[1]), "+f"((d)[2]), "+f"((d)[3]) \
        : "r"((a)[0]), "r"((a)[1]), "r"((a)[2]), "r"((a)[3]), "r"(b0), "r"(b1))

__device__ __forceinline__ void f2hilo(float v, __half& h, __half& l) {
    h = __float2half_rn(v);
    l = __float2half_rn(v - __half2float(h));
}

// ===================== scratch ==============================================
__device__ float g_qkv[(size_t)NTOK * 3 * BDIM];
__device__ float g_x1 [(size_t)NTOK * BDIM];
__device__ float g_h  [(size_t)NTOK * HID];
__device__ unsigned short g_xnh[(size_t)NTOK * BDIM], g_xnl[(size_t)NTOK * BDIM];
__device__ unsigned short g_ath[(size_t)NTOK * BDIM], g_atl[(size_t)NTOK * BDIM];
__device__ unsigned short g_hh [(size_t)NTOK * HID],  g_hl [(size_t)NTOK * HID];
__device__ unsigned short g_wqkvh[(size_t)3 * BDIM * BDIM];
__device__ unsigned short g_woh[(size_t)BDIM * BDIM];
__device__ unsigned short g_wuph[(size_t)HID * BDIM];
__device__ unsigned short g_wgh [(size_t)HID * BDIM];
__device__ unsigned short g_wdh [(size_t)BDIM * HID];

// ===================== convert fp32 -> fp16 (hi only, weights) =============
__global__ void cvt_h(const float* __restrict__ in, __half* __restrict__ hi, int n)
{
    int i4 = (blockIdx.x * blockDim.x + threadIdx.x) * 4;
    if (i4 >= n) return;
    float4 v = *(const float4*)(in + i4);
    *(__half2*)(hi + i4)     = __halves2half2(__float2half_rn(v.x), __float2half_rn(v.y));
    *(__half2*)(hi + i4 + 2) = __halves2half2(__float2half_rn(v.z), __float2half_rn(v.w));
}

// ===================== rmsnorm -> fp16 hi/lo ================================
__global__ void rmsnorm_hilo(const float* __restrict__ x,
                             const float* __restrict__ scale,
                             __half* __restrict__ ohi, __half* __restrict__ olo)
{
    int row = blockIdx.x;
    float4 v = ((const float4*)(x + (size_t)row * BDIM))[threadIdx.x];
    float ss = v.x * v.x + v.y * v.y + v.z * v.z + v.w * v.w;
    #pragma unroll
    for (int o = 16; o > 0; o >>= 1) ss += __shfl_xor_sync(0xffffffffu, ss, o);
    __shared__ float ws[8];
    if ((threadIdx.x & 31) == 0) ws[threadIdx.x >> 5] = ss;
    __syncthreads();
    float tot = ws[0] + ws[1] + ws[2] + ws[3] + ws[4] + ws[5] + ws[6] + ws[7];
    float inv = 1.0f / sqrtf(tot * (1.0f / BDIM) + EPSV);
    float4 sc = ((const float4*)scale)[threadIdx.x];
    float o0 = v.x * inv * sc.x, o1 = v.y * inv * sc.y;
    float o2 = v.z * inv * sc.z, o3 = v.w * inv * sc.w;
    __half h0, h1, h2, h3, l0, l1, l2, l3;
    f2hilo(o0, h0, l0); f2hilo(o1, h1, l1); f2hilo(o2, h2, l2); f2hilo(o3, h3, l3);
    size_t off = (size_t)row * BDIM + threadIdx.x * 4;
    *(__half2*)(ohi + off)     = __halves2half2(h0, h1);
    *(__half2*)(ohi + off + 2) = __halves2half2(h2, h3);
    *(__half2*)(olo + off)     = __halves2half2(l0, l1);
    *(__half2*)(olo + off + 2) = __halves2half2(l2, l3);
}

// ===================== HMMA fp16 2-pass GEMM ================================
// C[M,N] = (Ahi + Alo)[M,K] * Bh[N,K]^T ; fp32 accum.
// EPI 0: C = acc
// EPI 1: C = acc + R
// EPI 2: v = C * silu(acc); write v as fp16 hi/lo to O1/O2
#define BM 128
#define BN 128
#define BKE 32                      // fp16 elems per k-chunk
#define LDSB 80                     // padded row stride in bytes (32*2 + 16)
#define BUF_B (BM * LDSB)           // 10240 bytes per buffer
#define STG_B (3 * BUF_B)           // Ahi|Alo|Bh = 30720 bytes per stage
#define NSTAGE 4
#define GEMM_SMEM (NSTAGE * STG_B)  // 122880

template<int EPI>
__global__ __launch_bounds__(256, 1)
void gemm_hmma(const __half* __restrict__ Ahi, const __half* __restrict__ Alo,
               const __half* __restrict__ Bh,
               float* __restrict__ C, const float* __restrict__ R,
               __half* __restrict__ O1, __half* __restrict__ O2,
               int M, int N, int K)
{
    extern __shared__ char smem[];
    const uint32_t sb = smem_u32(smem);

    const int tid  = threadIdx.x;
    const int lane = tid & 31;
    const int wid  = tid >> 5;
    const int wm   = wid & 3;        // 4 warps along M
    const int wn   = wid >> 2;       // 2 warps along N
    const int bm = blockIdx.y * BM, bn = blockIdx.x * BN;

    // ---- global->shared load slots: per buffer, 2 x 16B chunks per thread
    const __half* gptr[3][2];
    uint32_t      sptr[3][2];
    {
        const __half* gsrc[3] = {Ahi, Alo, Bh};
        #pragma unroll
        for (int q = 0; q < 3; q++) {
            int rbase = (q < 2) ? bm : bn;
            #pragma unroll
            for (int j = 0; j < 2; j++) {
                int idx = tid * 2 + j;         // 0..511
                int row = idx >> 2, kc = idx & 3;
                gptr[q][j] = gsrc[q] + (size_t)(rbase + row) * K + kc * 8;
                sptr[q][j] = sb + q * BUF_B + row * LDSB + kc * 16;
            }
        }
    }

    const int nch = K / BKE;

    // prologue: fill NSTAGE stages
    #pragma unroll
    for (int s = 0; s < NSTAGE; s++) {
        #pragma unroll
        for (int q = 0; q < 3; q++)
            #pragma unroll
            for (int j = 0; j < 2; j++)
                CP_ASYNC16(sptr[q][j] + s * STG_B, gptr[q][j] + s * BKE);
        CP_COMMIT();
    }

    // ---- ldmatrix lane addressing
    const int a_row = lane & 15;
    const int a_k   = (lane >> 4) * 8;
    const uint32_t pA = sb + (wm * 32 + a_row) * LDSB + a_k * 2;
    const int b_n = (lane & 7) + ((lane >> 4) & 1) * 8;
    const int b_k = ((lane >> 3) & 1) * 8;
    const uint32_t pB = sb + 2 * BUF_B + (wn * 64 + b_n) * LDSB + b_k * 2;

    float acc[2][8][4];
    #pragma unroll
    for (int i = 0; i < 2; i++)
        #pragma unroll
        for (int j = 0; j < 8; j++)
            #pragma unroll
            for (int r = 0; r < 4; r++) acc[i][j][r] = 0.0f;

    for (int c = 0; c < nch; c++) {
        CP_WAIT3();
        __syncthreads();
        const uint32_t so = (c % NSTAGE) * STG_B;

        #pragma unroll
        for (int ks = 0; ks < 2; ks++) {
            uint32_t ah[2][4], al[2][4], bh[4][4];
            #pragma unroll
            for (int i = 0; i < 2; i++) {
                LDSM4(ah[i], pA + so + i * (16 * LDSB) + ks * 32);
                LDSM4(al[i], pA + so + i * (16 * LDSB) + ks * 32 + BUF_B);
            }
            #pragma unroll
            for (int j2 = 0; j2 < 4; j2++)
                LDSM4(bh[j2], pB + so + j2 * (16 * LDSB) + ks * 32);
            #pragma unroll
            for (int i = 0; i < 2; i++)
                #pragma unroll
                for (int j = 0; j < 8; j++) {
                    const int j2 = j >> 1, hh = (j & 1) * 2;
                    MMA16816(acc[i][j], ah[i], bh[j2][hh], bh[j2][hh + 1]);
                    MMA16816(acc[i][j], al[i], bh[j2][hh], bh[j2][hh + 1]);
                }
        }
        __syncthreads();

        const int cn = c + NSTAGE;
        if (cn < nch) {
            #pragma unroll
            for (int q = 0; q < 3; q++)
                #pragma unroll
                for (int j = 0; j < 2; j++)
                    CP_ASYNC16(sptr[q][j] + so, gptr[q][j] + cn * BKE);
        }
        CP_COMMIT();   // unconditional: keeps group count aligned in tail
    }

    // ---- epilogue
    const int g  = lane >> 2;
    const int c2 = (lane & 3) * 2;
    #pragma unroll
    for (int i = 0; i < 2; i++) {
        #pragma unroll
        for (int j = 0; j < 8; j++) {
            const int col = bn + wn * 64 + j * 8 + c2;
            const int r0 = bm + wm * 32 + i * 16 + g;
            #pragma unroll
            for (int hrow = 0; hrow < 2; hrow++) {
                const int row = r0 + hrow * 8;
                const size_t base = (size_t)row * N + col;
                float v0 = acc[i][j][hrow * 2 + 0];
                float v1 = acc[i][j][hrow * 2 + 1];
                if (EPI == 0) {
                    *(float2*)(C + base) = make_float2(v0, v1);
                } else if (EPI == 1) {
                    float2 rv = *(const float2*)(R + base);
                    *(float2*)(C + base) = make_float2(v0 + rv.x, v1 + rv.y);
                } else {
                    float2 u = *(const float2*)(C + base);
                    float s0 = u.x * (v0 / (1.0f + __expf(-v0)));
                    float s1 = u.y * (v1 / (1.0f + __expf(-v1)));
                    __half h0, h1, l0, l1;
                    f2hilo(s0, h0, l0); f2hilo(s1, h1, l1);
                    *(__half2*)(O1 + base) = __halves2half2(h0, h1);
                    *(__half2*)(O2 + base) = __halves2half2(l0, l1);
                }
            }
        }
    }
}

// ===================== flash attention (fp32, causal) -> fp16 hi/lo ========
#define ATT_SMEM_FLOATS (64 * 64 + 64 * 65 + 64 * 64)

__global__ __launch_bounds__(256, 2)
void flash_attn_kernel(const float* __restrict__ qkv,
                       __half* __restrict__ ahi, __half* __restrict__ alo2)
{
    extern __shared__ float sm[];
    float* Qs = sm;
    float* Ks = sm + 64 * 64;
    float* Vs = Ks + 64 * 65;

    const int qb = blockIdx.x, hd = blockIdx.y, b = blockIdx.z;
    const int q0 = qb * 64;
    const int tid = threadIdx.x;
    const int tx = tid & 15, ty = tid >> 4;
    const int ld = 3 * BDIM;

    const float* qbase = qkv + ((size_t)(b * SEQ + q0)) * ld + hd * DHEAD;
    #pragma unroll
    for (int i = 0; i < 4; i++) {
        int f = tid + i * 256;
        int r = f >> 4, c4 = f & 15;
        *(float4*)(Qs + r * 64 + c4 * 4) = *(const float4*)(qbase + (size_t)r * ld + c4 * 4);
    }

    float o[4][4], mrow[4], lsum[4];
    #pragma unroll
    for (int i = 0; i < 4; i++) {
        mrow[i] = -3.0e38f; lsum[i] = 0.0f;
        #pragma unroll
        for (int j = 0; j < 4; j++) o[i][j] = 0.0f;
    }

    const float* kbase = qkv + (size_t)(b * SEQ) * ld + BDIM     + hd * DHEAD;
    const float* vbase = qkv + (size_t)(b * SEQ) * ld + 2 * BDIM + hd * DHEAD;

    const int ntiles = qb + 1;
    for (int t = 0; t < ntiles; t++) {
        const int kv0 = t * 64;
        __syncthreads();
        #pragma unroll
        for (int i = 0; i < 4; i++) {
            int f = tid + i * 256;
            int r = f >> 4, c4 = f & 15;
            float4 kvv = *(const float4*)(kbase + (size_t)(kv0 + r) * ld + c4 * 4);
            Ks[r * 65 + c4 * 4 + 0] = kvv.x;
            Ks[r * 65 + c4 * 4 + 1] = kvv.y;
            Ks[r * 65 + c4 * 4 + 2] = kvv.z;
            Ks[r * 65 + c4 * 4 + 3] = kvv.w;
            *(float4*)(Vs + r * 64 + c4 * 4) = *(const float4*)(vbase + (size_t)(kv0 + r) * ld + c4 * 4);
        }
        __syncthreads();

        float s[4][4];
        #pragma unroll
        for (int i = 0; i < 4; i++)
            #pragma unroll
            for (int j = 0; j < 4; j++) s[i][j] = 0.0f;
        #pragma unroll 4
        for (int kd = 0; kd < 64; kd++) {
            float a[4], bb[4];
            #pragma unroll
            for (int i = 0; i < 4; i++) a[i]  = Qs[(ty * 4 + i) * 64 + kd];
            #pragma unroll
            for (int j = 0; j < 4; j++) bb[j] = Ks[(tx * 4 + j) * 65 + kd];
            #pragma unroll
            for (int i = 0; i < 4; i++)
                #pragma unroll
                for (int j = 0; j < 4; j++) s[i][j] = fmaf(a[i], bb[j], s[i][j]);
        }

        const float scale = 0.125f;
        if (t == ntiles - 1) {
            #pragma unroll
            for (int i = 0; i < 4; i++)
                #pragma unroll
                for (int j = 0; j < 4; j++)
                    s[i][j] = (tx * 4 + j > ty * 4 + i) ? -3.0e38f : s[i][j] * scale;
        } else {
            #pragma unroll
            for (int i = 0; i < 4; i++)
                #pragma unroll
                for (int j = 0; j < 4; j++) s[i][j] *= scale;
        }

        #pragma unroll
        for (int i = 0; i < 4; i++) {
            float mx = fmaxf(fmaxf(s[i][0], s[i][1]), fmaxf(s[i][2], s[i][3]));
            #pragma unroll
            for (int od = 8; od > 0; od >>= 1)
                mx = fmaxf(mx, __shfl_xor_sync(0xffffffffu, mx, od));
            float mnew = fmaxf(mrow[i], mx);
            float fac = __expf(mrow[i] - mnew);
            float ps = 0.0f;
            #pragma unroll
            for (int j = 0; j < 4; j++) { s[i][j] = __expf(s[i][j] - mnew); ps += s[i][j]; }
            #pragma unroll
            for (int od = 8; od > 0; od >>= 1)
                ps += __shfl_xor_sync(0xffffffffu, ps, od);
            lsum[i] = lsum[i] * fac + ps;
            mrow[i] = mnew;
            #pragma unroll
            for (int j = 0; j < 4; j++) o[i][j] *= fac;
        }

        __syncthreads();
        float* Ps = Ks;
        #pragma unroll
        for (int i = 0; i < 4; i++)
            #pragma unroll
            for (int j = 0; j < 4; j++)
                Ps[(ty * 4 + i) * 65 + tx * 4 + j] = s[i][j];
        __syncthreads();

        #pragma unroll 4
        for (int kv = 0; kv < 64; kv++) {
            float p[4], vv[4];
            #pragma unroll
            for (int i = 0; i < 4; i++) p[i] = Ps[(ty * 4 + i) * 65 + kv];
            *(float4*)&vv[0] = *(const float4*)(Vs + kv * 64 + tx * 4);
            #pragma unroll
            for (int i = 0; i < 4; i++)
                #pragma unroll
                for (int j = 0; j < 4; j++) o[i][j] = fmaf(p[i], vv[j], o[i][j]);
        }
    }

    #pragma unroll
    for (int i = 0; i < 4; i++) {
        float invl = 1.0f / lsum[i];
        int r = q0 + ty * 4 + i;
        __half h[4], l[4];
        #pragma unroll
        for (int j = 0; j < 4; j++) f2hilo(o[i][j] * invl, h[j], l[j]);
        size_t off = ((size_t)(b * SEQ) + r) * BDIM + hd * DHEAD + tx * 4;
        *(__half2*)(ahi + off)      = __halves2half2(h[0], h[1]);
        *(__half2*)(ahi + off + 2)  = __halves2half2(h[2], h[3]);
        *(__half2*)(alo2 + off)     = __halves2half2(l[0], l[1]);
        *(__half2*)(alo2 + off + 2) = __halves2half2(l[2], l[3]);
    }
}

// ===================== launch ==============================================
extern "C" void kernel_launch(void* const* d_in, const int* in_sizes, int n_in,
                              void* d_out, int out_size)
{
    const float* x      = (const float*)d_in[0];
    const float* w_qkv  = (const float*)d_in[1];
    const float* w_o    = (const float*)d_in[2];
    const float* w_up   = (const float*)d_in[3];
    const float* w_gate = (const float*)d_in[4];
    const float* w_down = (const float*)d_in[5];
    const float* scale1 = (const float*)d_in[6];
    const float* scale2 = (const float*)d_in[7];
    float* out = (float*)d_out;

    float *qkvb, *x1, *hbuf;
    __half *xnh, *xnl, *ath, *atl, *hh, *hl;
    __half *wqkvh, *woh, *wuph, *wgh, *wdh;
    cudaGetSymbolAddress((void**)&qkvb, g_qkv);
    cudaGetSymbolAddress((void**)&x1,   g_x1);
    cudaGetSymbolAddress((void**)&hbuf, g_h);
    cudaGetSymbolAddress((void**)&xnh, g_xnh);  cudaGetSymbolAddress((void**)&xnl, g_xnl);
    cudaGetSymbolAddress((void**)&ath, g_ath);  cudaGetSymbolAddress((void**)&atl, g_atl);
    cudaGetSymbolAddress((void**)&hh,  g_hh);   cudaGetSymbolAddress((void**)&hl,  g_hl);
    cudaGetSymbolAddress((void**)&wqkvh, g_wqkvh);
    cudaGetSymbolAddress((void**)&woh, g_woh);
    cudaGetSymbolAddress((void**)&wuph, g_wuph);
    cudaGetSymbolAddress((void**)&wgh, g_wgh);
    cudaGetSymbolAddress((void**)&wdh, g_wdh);

    const int att_smem = ATT_SMEM_FLOATS * (int)sizeof(float);
    cudaFuncSetAttribute(flash_attn_kernel,
                         cudaFuncAttributeMaxDynamicSharedMemorySize, att_smem);
    cudaFuncSetAttribute(gemm_hmma<0>,
                         cudaFuncAttributeMaxDynamicSharedMemorySize, GEMM_SMEM);
    cudaFuncSetAttribute(gemm_hmma<1>,
                         cudaFuncAttributeMaxDynamicSharedMemorySize, GEMM_SMEM);
    cudaFuncSetAttribute(gemm_hmma<2>,
                         cudaFuncAttributeMaxDynamicSharedMemorySize, GEMM_SMEM);

    // weight conversion (fp16 hi only)
    {
        int n;
        n = 3 * BDIM * BDIM; cvt_h<<<(n/4 + 255)/256, 256>>>(w_qkv,  wqkvh, n);
        n = BDIM * BDIM;     cvt_h<<<(n/4 + 255)/256, 256>>>(w_o,    woh,   n);
        n = HID * BDIM;      cvt_h<<<(n/4 + 255)/256, 256>>>(w_up,   wuph,  n);
        n = HID * BDIM;      cvt_h<<<(n/4 + 255)/256, 256>>>(w_gate, wgh,   n);
        n = BDIM * HID;      cvt_h<<<(n/4 + 255)/256, 256>>>(w_down, wdh,   n);
    }

    // 1. xn = rmsnorm(x, scale1)  (fp16 hi/lo)
    rmsnorm_hilo<<<NTOK, 256>>>(x, scale1, xnh, xnl);

    // 2. qkv = xn @ w_qkv.T  (fp32)
    {
        dim3 g(3 * BDIM / BN, NTOK / BM);
        gemm_hmma<0><<<g, 256, GEMM_SMEM>>>(xnh, xnl, wqkvh,
                                            qkvb, nullptr, nullptr, nullptr,
                                            NTOK, 3 * BDIM, BDIM);
    }

    // 3. attention core -> attn (fp16 hi/lo)
    {
        dim3 g(SEQ / 64, NHEAD, BATCH);
        flash_attn_kernel<<<g, 256, att_smem>>>(qkvb, ath, atl);
    }

    // 4. x1 = x + attn @ w_o.T
    {
        dim3 g(BDIM / BN, NTOK / BM);
        gemm_hmma<1><<<g, 256, GEMM_SMEM>>>(ath, atl, woh,
                                            x1, x, nullptr, nullptr,
                                            NTOK, BDIM, BDIM);
    }

    // 5. xn = rmsnorm(x1, scale2)
    rmsnorm_hilo<<<NTOK, 256>>>(x1, scale2, xnh, xnl);

    // 6. h = xn @ w_up.T (fp32); 7. h = h * silu(xn @ w_gate.T) -> fp16 hi/lo
    {
        dim3 g(HID / BN, NTOK / BM);
        gemm_hmma<0><<<g, 256, GEMM_SMEM>>>(xnh, xnl, wuph,
                                            hbuf, nullptr, nullptr, nullptr,
                                            NTOK, HID, BDIM);
        gemm_hmma<2><<<g, 256, GEMM_SMEM>>>(xnh, xnl, wgh,
                                            hbuf, nullptr, hh, hl,
                                            NTOK, HID, BDIM);
    }

    // 8. out = x1 + h @ w_down.T
    {
        dim3 g(BDIM / BN, NTOK / BM);
        gemm_hmma<1><<<g, 256, GEMM_SMEM>>>(hh, hl, wdh,
                                            out, x1, nullptr, nullptr,
                                            NTOK, BDIM, HID);
    }
}

// round 5
// speedup vs baseline: 4.8666x; 2.1395x over previous
#include <cuda_runtime.h>
#include <cuda_fp16.h>
#include <cstdint>
#include <math.h>

#define BDIM   1024
#define NHEAD  16
#define DHEAD  64
#define SEQ    2048
#define BATCH  2
#define NTOK   (BATCH * SEQ)      // 4096
#define HID    (4 * BDIM)         // 4096
#define EPSV   1e-6f

// ===================== helpers =============================================
__device__ __forceinline__ uint32_t smem_u32(const void* p) {
    uint32_t a;
    asm("{ .reg .u64 t; cvta.to.shared.u64 t, %1; cvt.u32.u64 %0, t; }"
        : "=r"(a) : "l"(p));
    return a;
}

#define CP_ASYNC16(s, g) \
    asm volatile("cp.async.cg.shared.global [%0], [%1], 16;" :: "r"(s), "l"(g))
#define CP_COMMIT() asm volatile("cp.async.commit_group;" ::: "memory")
#define CP_WAIT()   asm volatile("cp.async.wait_group 4;" ::: "memory")

#define LDSM4(r, a) \
    asm volatile("ldmatrix.sync.aligned.m8n8.x4.shared.b16 {%0,%1,%2,%3}, [%4];" \
        : "=r"((r)[0]), "=r"((r)[1]), "=r"((r)[2]), "=r"((r)[3]) : "r"(a))
#define LDSM4T(r, a) \
    asm volatile("ldmatrix.sync.aligned.m8n8.x4.trans.shared.b16 {%0,%1,%2,%3}, [%4];" \
        : "=r"((r)[0]), "=r"((r)[1]), "=r"((r)[2]), "=r"((r)[3]) : "r"(a))

#define MMA16816(d, a, b0, b1) \
    asm volatile("mma.sync.aligned.m16n8k16.row.col.f32.f16.f16.f32 " \
        "{%0,%1,%2,%3}, {%4,%5,%6,%7}, {%8,%9}, {%0,%1,%2,%3};" \
        : "+f"((d)[0]), "+f"((d)[1]), "+f"((d)[2]), "+f"((d)[3]) \
        : "r"((a)[0]), "r"((a)[1]), "r"((a)[2]), "r"((a)[3]), "r"(b0), "r"(b1))

__device__ __forceinline__ uint32_t packh2(float a, float b) {
    __half2 h = __floats2half2_rn(a, b);
    return *(uint32_t*)&h;
}

// ===================== scratch ==============================================
__device__ float g_qkv[(size_t)NTOK * 3 * BDIM];
__device__ float g_x1 [(size_t)NTOK * BDIM];
__device__ float g_h  [(size_t)NTOK * HID];
__device__ unsigned short g_xnh[(size_t)NTOK * BDIM];
__device__ unsigned short g_ath[(size_t)NTOK * BDIM];
__device__ unsigned short g_hh [(size_t)NTOK * HID];
__device__ unsigned short g_wqkvh[(size_t)3 * BDIM * BDIM];
__device__ unsigned short g_woh[(size_t)BDIM * BDIM];
__device__ unsigned short g_wuph[(size_t)HID * BDIM];
__device__ unsigned short g_wgh [(size_t)HID * BDIM];
__device__ unsigned short g_wdh [(size_t)BDIM * HID];

// ===================== convert fp32 -> fp16 (weights) ======================
__global__ void cvt_h(const float* __restrict__ in, __half* __restrict__ hi, int n)
{
    int i4 = (blockIdx.x * blockDim.x + threadIdx.x) * 4;
    if (i4 >= n) return;
    float4 v = *(const float4*)(in + i4);
    *(__half2*)(hi + i4)     = __floats2half2_rn(v.x, v.y);
    *(__half2*)(hi + i4 + 2) = __floats2half2_rn(v.z, v.w);
}

// ===================== rmsnorm -> fp16 ======================================
__global__ void rmsnorm_h(const float* __restrict__ x,
                          const float* __restrict__ scale,
                          __half* __restrict__ ohi)
{
    int row = blockIdx.x;
    float4 v = ((const float4*)(x + (size_t)row * BDIM))[threadIdx.x];
    float ss = v.x * v.x + v.y * v.y + v.z * v.z + v.w * v.w;
    #pragma unroll
    for (int o = 16; o > 0; o >>= 1) ss += __shfl_xor_sync(0xffffffffu, ss, o);
    __shared__ float ws[8];
    if ((threadIdx.x & 31) == 0) ws[threadIdx.x >> 5] = ss;
    __syncthreads();
    float tot = ws[0] + ws[1] + ws[2] + ws[3] + ws[4] + ws[5] + ws[6] + ws[7];
    float inv = 1.0f / sqrtf(tot * (1.0f / BDIM) + EPSV);
    float4 sc = ((const float4*)scale)[threadIdx.x];
    size_t off = (size_t)row * BDIM + threadIdx.x * 4;
    *(__half2*)(ohi + off)     = __floats2half2_rn(v.x * inv * sc.x, v.y * inv * sc.y);
    *(__half2*)(ohi + off + 2) = __floats2half2_rn(v.z * inv * sc.z, v.w * inv * sc.w);
}

// ===================== HMMA fp16 1-pass GEMM ================================
// C[M,N] = Ah[M,K] * Bh[N,K]^T ; fp32 accum.
// EPI 0: C = acc ; EPI 1: C = acc + R ; EPI 2: O1 = h(C * silu(acc))
#define BM 128
#define BN 128
#define BKE 32                      // fp16 elems per k-chunk
#define LDSB 80                     // padded row stride in bytes
#define BUF_B (BM * LDSB)           // 10240 bytes per buffer
#define STG_B (2 * BUF_B)           // Ah|Bh = 20480 bytes per stage
#define NSTAGE 5
#define GEMM_SMEM (NSTAGE * STG_B)  // 102400

template<int EPI>
__global__ __launch_bounds__(256, 1)
void gemm_hmma(const __half* __restrict__ Ah, const __half* __restrict__ Bh,
               float* __restrict__ C, const float* __restrict__ R,
               __half* __restrict__ O1,
               int M, int N, int K)
{
    extern __shared__ char smem[];
    const uint32_t sb = smem_u32(smem);

    const int tid  = threadIdx.x;
    const int lane = tid & 31;
    const int wid  = tid >> 5;
    const int wm   = wid & 3;        // 4 warps along M
    const int wn   = wid >> 2;       // 2 warps along N
    const int bm = blockIdx.y * BM, bn = blockIdx.x * BN;

    const __half* gptr[2][2];
    uint32_t      sptr[2][2];
    {
        const __half* gsrc[2] = {Ah, Bh};
        #pragma unroll
        for (int q = 0; q < 2; q++) {
            int rbase = (q == 0) ? bm : bn;
            #pragma unroll
            for (int j = 0; j < 2; j++) {
                int idx = tid * 2 + j;         // 0..511
                int row = idx >> 2, kc = idx & 3;
                gptr[q][j] = gsrc[q] + (size_t)(rbase + row) * K + kc * 8;
                sptr[q][j] = sb + q * BUF_B + row * LDSB + kc * 16;
            }
        }
    }

    const int nch = K / BKE;

    #pragma unroll
    for (int s = 0; s < NSTAGE; s++) {
        #pragma unroll
        for (int q = 0; q < 2; q++)
            #pragma unroll
            for (int j = 0; j < 2; j++)
                CP_ASYNC16(sptr[q][j] + s * STG_B, gptr[q][j] + s * BKE);
        CP_COMMIT();
    }

    const uint32_t pA = sb + (wm * 32 + (lane & 15)) * LDSB + ((lane >> 4) * 8) * 2;
    const int b_n = (lane & 7) + ((lane >> 4) & 1) * 8;
    const int b_k = ((lane >> 3) & 1) * 8;
    const uint32_t pB = sb + BUF_B + (wn * 64 + b_n) * LDSB + b_k * 2;

    float acc[2][8][4];
    #pragma unroll
    for (int i = 0; i < 2; i++)
        #pragma unroll
        for (int j = 0; j < 8; j++)
            #pragma unroll
            for (int r = 0; r < 4; r++) acc[i][j][r] = 0.0f;

    for (int c = 0; c < nch; c++) {
        CP_WAIT();
        __syncthreads();
        const uint32_t so = (c % NSTAGE) * STG_B;

        #pragma unroll
        for (int ks = 0; ks < 2; ks++) {
            uint32_t ah[2][4], bh[4][4];
            #pragma unroll
            for (int i = 0; i < 2; i++)
                LDSM4(ah[i], pA + so + i * (16 * LDSB) + ks * 32);
            #pragma unroll
            for (int j2 = 0; j2 < 4; j2++)
                LDSM4(bh[j2], pB + so + j2 * (16 * LDSB) + ks * 32);
            #pragma unroll
            for (int i = 0; i < 2; i++)
                #pragma unroll
                for (int j = 0; j < 8; j++) {
                    const int j2 = j >> 1, hh = (j & 1) * 2;
                    MMA16816(acc[i][j], ah[i], bh[j2][hh], bh[j2][hh + 1]);
                }
        }
        __syncthreads();

        const int cn = c + NSTAGE;
        if (cn < nch) {
            #pragma unroll
            for (int q = 0; q < 2; q++)
                #pragma unroll
                for (int j = 0; j < 2; j++)
                    CP_ASYNC16(sptr[q][j] + so, gptr[q][j] + cn * BKE);
        }
        CP_COMMIT();
    }

    const int g  = lane >> 2;
    const int c2 = (lane & 3) * 2;
    #pragma unroll
    for (int i = 0; i < 2; i++) {
        #pragma unroll
        for (int j = 0; j < 8; j++) {
            const int col = bn + wn * 64 + j * 8 + c2;
            const int r0 = bm + wm * 32 + i * 16 + g;
            #pragma unroll
            for (int hrow = 0; hrow < 2; hrow++) {
                const int row = r0 + hrow * 8;
                const size_t base = (size_t)row * N + col;
                float v0 = acc[i][j][hrow * 2 + 0];
                float v1 = acc[i][j][hrow * 2 + 1];
                if (EPI == 0) {
                    *(float2*)(C + base) = make_float2(v0, v1);
                } else if (EPI == 1) {
                    float2 rv = *(const float2*)(R + base);
                    *(float2*)(C + base) = make_float2(v0 + rv.x, v1 + rv.y);
                } else {
                    float2 u = *(const float2*)(C + base);
                    float s0 = u.x * (v0 / (1.0f + __expf(-v0)));
                    float s1 = u.y * (v1 / (1.0f + __expf(-v1)));
                    *(__half2*)(O1 + base) = __floats2half2_rn(s0, s1);
                }
            }
        }
    }
}

// ===================== fp16 HMMA flash attention ===========================
// block: 64 q-rows, one head. 128 threads = 4 warps, each warp 16 q-rows.
#define ASTRIDE 72                  // halves per smem row (144 B, 16B multiple)

__global__ __launch_bounds__(128)
void flash_attn_hmma(const float* __restrict__ qkv, __half* __restrict__ outh)
{
    __shared__ __half Qs[64][ASTRIDE];
    __shared__ __half Ks[64][ASTRIDE];
    __shared__ __half Vs[64][ASTRIDE];

    const int qb = blockIdx.x, hd = blockIdx.y, b = blockIdx.z;
    const int q0 = qb * 64;
    const int tid = threadIdx.x, lane = tid & 31, wid = tid >> 5;
    const int ld = 3 * BDIM;
    const int g = lane >> 2, c2 = lane & 3;

    // load Q tile (fp32 -> fp16)
    const float* qbase = qkv + ((size_t)(b * SEQ + q0)) * ld + hd * DHEAD;
    #pragma unroll
    for (int i = 0; i < 8; i++) {
        int idx = tid + i * 128;            // 0..1023 float4 slots
        int r = idx >> 4, c4 = (idx & 15) * 4;
        float4 v = *(const float4*)(qbase + (size_t)r * ld + c4);
        *(__half2*)&Qs[r][c4]     = __floats2half2_rn(v.x, v.y);
        *(__half2*)&Qs[r][c4 + 2] = __floats2half2_rn(v.z, v.w);
    }

    const float* kbase = qkv + (size_t)(b * SEQ) * ld + BDIM     + hd * DHEAD;
    const float* vbase = qkv + (size_t)(b * SEQ) * ld + 2 * BDIM + hd * DHEAD;

    float o[8][4];
    #pragma unroll
    for (int j = 0; j < 8; j++)
        #pragma unroll
        for (int r = 0; r < 4; r++) o[j][r] = 0.0f;
    float mrow[2] = {-1e30f, -1e30f}, lsum[2] = {0.0f, 0.0f};

    // ldmatrix base addresses
    const uint32_t qaddr = smem_u32(&Qs[wid * 16 + (lane & 15)][(lane >> 4) * 8]);
    const uint32_t kaddr = smem_u32(&Ks[(lane & 7) + ((lane >> 4) & 1) * 8]
                                       [((lane >> 3) & 1) * 8]);
    const uint32_t vaddr = smem_u32(&Vs[(lane & 7) + ((lane >> 3) & 1) * 8]
                                       [((lane >> 4) & 1) * 8]);

    const int ntiles = qb + 1;
    const int qrow0 = q0 + wid * 16 + g;    // this thread's q rows: qrow0, qrow0+8

    for (int t = 0; t < ntiles; t++) {
        const int kv0 = t * 64;
        __syncthreads();
        #pragma unroll
        for (int i = 0; i < 8; i++) {
            int idx = tid + i * 128;
            int r = idx >> 4, c4 = (idx & 15) * 4;
            float4 kv = *(const float4*)(kbase + (size_t)(kv0 + r) * ld + c4);
            *(__half2*)&Ks[r][c4]     = __floats2half2_rn(kv.x, kv.y);
            *(__half2*)&Ks[r][c4 + 2] = __floats2half2_rn(kv.z, kv.w);
            float4 vv = *(const float4*)(vbase + (size_t)(kv0 + r) * ld + c4);
            *(__half2*)&Vs[r][c4]     = __floats2half2_rn(vv.x, vv.y);
            *(__half2*)&Vs[r][c4 + 2] = __floats2half2_rn(vv.z, vv.w);
        }
        __syncthreads();

        // ---- S = Q K^T : s[8 n-tiles][4]
        float s[8][4];
        #pragma unroll
        for (int j = 0; j < 8; j++)
            #pragma unroll
            for (int r = 0; r < 4; r++) s[j][r] = 0.0f;
        #pragma unroll
        for (int kk = 0; kk < 4; kk++) {
            uint32_t qa[4];
            LDSM4(qa, qaddr + kk * 32);
            #pragma unroll
            for (int j2 = 0; j2 < 4; j2++) {
                uint32_t kb[4];
                LDSM4(kb, kaddr + j2 * (16 * ASTRIDE * 2) + kk * 32);
                MMA16816(s[2 * j2],     qa, kb[0], kb[1]);
                MMA16816(s[2 * j2 + 1], qa, kb[2], kb[3]);
            }
        }

        // ---- scale + causal mask
        const float scale = 0.125f;
        if (t == ntiles - 1) {
            #pragma unroll
            for (int j = 0; j < 8; j++) {
                int col = kv0 + j * 8 + c2 * 2;
                s[j][0] = (col     > qrow0)     ? -1e30f : s[j][0] * scale;
                s[j][1] = (col + 1 > qrow0)     ? -1e30f : s[j][1] * scale;
                s[j][2] = (col     > qrow0 + 8) ? -1e30f : s[j][2] * scale;
                s[j][3] = (col + 1 > qrow0 + 8) ? -1e30f : s[j][3] * scale;
            }
        } else {
            #pragma unroll
            for (int j = 0; j < 8; j++)
                #pragma unroll
                for (int r = 0; r < 4; r++) s[j][r] *= scale;
        }

        // ---- online softmax (rows qrow0 / qrow0+8)
        float mx0 = -1e30f, mx1 = -1e30f;
        #pragma unroll
        for (int j = 0; j < 8; j++) {
            mx0 = fmaxf(mx0, fmaxf(s[j][0], s[j][1]));
            mx1 = fmaxf(mx1, fmaxf(s[j][2], s[j][3]));
        }
        mx0 = fmaxf(mx0, __shfl_xor_sync(0xffffffffu, mx0, 1));
        mx0 = fmaxf(mx0, __shfl_xor_sync(0xffffffffu, mx0, 2));
        mx1 = fmaxf(mx1, __shfl_xor_sync(0xffffffffu, mx1, 1));
        mx1 = fmaxf(mx1, __shfl_xor_sync(0xffffffffu, mx1, 2));
        float mn0 = fmaxf(mrow[0], mx0), mn1 = fmaxf(mrow[1], mx1);
        float fac0 = __expf(mrow[0] - mn0), fac1 = __expf(mrow[1] - mn1);
        float ps0 = 0.0f, ps1 = 0.0f;
        #pragma unroll
        for (int j = 0; j < 8; j++) {
            s[j][0] = __expf(s[j][0] - mn0);
            s[j][1] = __expf(s[j][1] - mn0);
            s[j][2] = __expf(s[j][2] - mn1);
            s[j][3] = __expf(s[j][3] - mn1);
            ps0 += s[j][0] + s[j][1];
            ps1 += s[j][2] + s[j][3];
        }
        ps0 += __shfl_xor_sync(0xffffffffu, ps0, 1);
        ps0 += __shfl_xor_sync(0xffffffffu, ps0, 2);
        ps1 += __shfl_xor_sync(0xffffffffu, ps1, 1);
        ps1 += __shfl_xor_sync(0xffffffffu, ps1, 2);
        lsum[0] = lsum[0] * fac0 + ps0;  mrow[0] = mn0;
        lsum[1] = lsum[1] * fac1 + ps1;  mrow[1] = mn1;
        #pragma unroll
        for (int j = 0; j < 8; j++) {
            o[j][0] *= fac0; o[j][1] *= fac0;
            o[j][2] *= fac1; o[j][3] *= fac1;
        }

        // ---- P fragments (D layout -> A layout repack)
        uint32_t pa[4][4];
        #pragma unroll
        for (int kk = 0; kk < 4; kk++) {
            pa[kk][0] = packh2(s[2 * kk][0],     s[2 * kk][1]);
            pa[kk][1] = packh2(s[2 * kk][2],     s[2 * kk][3]);
            pa[kk][2] = packh2(s[2 * kk + 1][0], s[2 * kk + 1][1]);
            pa[kk][3] = packh2(s[2 * kk + 1][2], s[2 * kk + 1][3]);
        }

        // ---- O += P V  (V via ldmatrix.trans)
        #pragma unroll
        for (int j2 = 0; j2 < 4; j2++) {
            #pragma unroll
            for (int kk = 0; kk < 4; kk++) {
                uint32_t vb[4];
                LDSM4T(vb, vaddr + kk * (16 * ASTRIDE * 2) + j2 * 32);
                MMA16816(o[2 * j2],     pa[kk], vb[0], vb[1]);
                MMA16816(o[2 * j2 + 1], pa[kk], vb[2], vb[3]);
            }
        }
    }

    // ---- epilogue
    float inv0 = 1.0f / lsum[0], inv1 = 1.0f / lsum[1];
    const size_t rbase0 = ((size_t)(b * SEQ) + qrow0) * BDIM + hd * DHEAD;
    const size_t rbase1 = rbase0 + (size_t)8 * BDIM;
    #pragma unroll
    for (int j = 0; j < 8; j++) {
        int col = j * 8 + c2 * 2;
        *(__half2*)(outh + rbase0 + col) = __floats2half2_rn(o[j][0] * inv0, o[j][1] * inv0);
        *(__half2*)(outh + rbase1 + col) = __floats2half2_rn(o[j][2] * inv1, o[j][3] * inv1);
    }
}

// ===================== launch ==============================================
extern "C" void kernel_launch(void* const* d_in, const int* in_sizes, int n_in,
                              void* d_out, int out_size)
{
    const float* x      = (const float*)d_in[0];
    const float* w_qkv  = (const float*)d_in[1];
    const float* w_o    = (const float*)d_in[2];
    const float* w_up   = (const float*)d_in[3];
    const float* w_gate = (const float*)d_in[4];
    const float* w_down = (const float*)d_in[5];
    const float* scale1 = (const float*)d_in[6];
    const float* scale2 = (const float*)d_in[7];
    float* out = (float*)d_out;

    float *qkvb, *x1, *hbuf;
    __half *xnh, *ath, *hh;
    __half *wqkvh, *woh, *wuph, *wgh, *wdh;
    cudaGetSymbolAddress((void**)&qkvb, g_qkv);
    cudaGetSymbolAddress((void**)&x1,   g_x1);
    cudaGetSymbolAddress((void**)&hbuf, g_h);
    cudaGetSymbolAddress((void**)&xnh, g_xnh);
    cudaGetSymbolAddress((void**)&ath, g_ath);
    cudaGetSymbolAddress((void**)&hh,  g_hh);
    cudaGetSymbolAddress((void**)&wqkvh, g_wqkvh);
    cudaGetSymbolAddress((void**)&woh, g_woh);
    cudaGetSymbolAddress((void**)&wuph, g_wuph);
    cudaGetSymbolAddress((void**)&wgh, g_wgh);
    cudaGetSymbolAddress((void**)&wdh, g_wdh);

    cudaFuncSetAttribute(gemm_hmma<0>,
                         cudaFuncAttributeMaxDynamicSharedMemorySize, GEMM_SMEM);
    cudaFuncSetAttribute(gemm_hmma<1>,
                         cudaFuncAttributeMaxDynamicSharedMemorySize, GEMM_SMEM);
    cudaFuncSetAttribute(gemm_hmma<2>,
                         cudaFuncAttributeMaxDynamicSharedMemorySize, GEMM_SMEM);

    // weight conversion (fp16)
    {
        int n;
        n = 3 * BDIM * BDIM; cvt_h<<<(n/4 + 255)/256, 256>>>(w_qkv,  wqkvh, n);
        n = BDIM * BDIM;     cvt_h<<<(n/4 + 255)/256, 256>>>(w_o,    woh,   n);
        n = HID * BDIM;      cvt_h<<<(n/4 + 255)/256, 256>>>(w_up,   wuph,  n);
        n = HID * BDIM;      cvt_h<<<(n/4 + 255)/256, 256>>>(w_gate, wgh,   n);
        n = BDIM * HID;      cvt_h<<<(n/4 + 255)/256, 256>>>(w_down, wdh,   n);
    }

    // 1. xn = rmsnorm(x, scale1) -> fp16
    rmsnorm_h<<<NTOK, 256>>>(x, scale1, xnh);

    // 2. qkv = xn @ w_qkv.T (fp32)
    {
        dim3 g(3 * BDIM / BN, NTOK / BM);
        gemm_hmma<0><<<g, 256, GEMM_SMEM>>>(xnh, wqkvh, qkvb, nullptr, nullptr,
                                            NTOK, 3 * BDIM, BDIM);
    }

    // 3. attention core -> ath (fp16)
    {
        dim3 g(SEQ / 64, NHEAD, BATCH);
        flash_attn_hmma<<<g, 128>>>(qkvb, ath);
    }

    // 4. x1 = x + attn @ w_o.T
    {
        dim3 g(BDIM / BN, NTOK / BM);
        gemm_hmma<1><<<g, 256, GEMM_SMEM>>>(ath, woh, x1, x, nullptr,
                                            NTOK, BDIM, BDIM);
    }

    // 5. xn = rmsnorm(x1, scale2) -> fp16
    rmsnorm_h<<<NTOK, 256>>>(x1, scale2, xnh);

    // 6. h = xn @ w_up.T (fp32); 7. hh = h * silu(xn @ w_gate.T) (fp16)
    {
        dim3 g(HID / BN, NTOK / BM);
        gemm_hmma<0><<<g, 256, GEMM_SMEM>>>(xnh, wuph, hbuf, nullptr, nullptr,
                                            NTOK, HID, BDIM);
        gemm_hmma<2><<<g, 256, GEMM_SMEM>>>(xnh, wgh, hbuf, nullptr, hh,
                                            NTOK, HID, BDIM);
    }

    // 8. out = x1 + hh @ w_down.T
    {
        dim3 g(BDIM / BN, NTOK / BM);
        gemm_hmma<1><<<g, 256, GEMM_SMEM>>>(hh, wdh, out, x1, nullptr,
                                            NTOK, BDIM, HID);
    }
}

// round 6
// speedup vs baseline: 5.6517x; 1.1613x over previous
#include <cuda_runtime.h>
#include <cuda_fp16.h>
#include <cstdint>
#include <math.h>

#define BDIM   1024
#define NHEAD  16
#define DHEAD  64
#define SEQ    2048
#define BATCH  2
#define NTOK   (BATCH * SEQ)      // 4096
#define HID    (4 * BDIM)         // 4096
#define EPSV   1e-6f

// ===================== helpers =============================================
__device__ __forceinline__ uint32_t smem_u32(const void* p) {
    uint32_t a;
    asm("{ .reg .u64 t; cvta.to.shared.u64 t, %1; cvt.u32.u64 %0, t; }"
        : "=r"(a) : "l"(p));
    return a;
}

#define CP_ASYNC16(s, g) \
    asm volatile("cp.async.cg.shared.global [%0], [%1], 16;" :: "r"(s), "l"(g))
#define CP_COMMIT() asm volatile("cp.async.commit_group;" ::: "memory")
#define CP_WAIT4()  asm volatile("cp.async.wait_group 4;" ::: "memory")
#define CP_WAIT3()  asm volatile("cp.async.wait_group 3;" ::: "memory")

#define LDSM4(r, a) \
    asm volatile("ldmatrix.sync.aligned.m8n8.x4.shared.b16 {%0,%1,%2,%3}, [%4];" \
        : "=r"((r)[0]), "=r"((r)[1]), "=r"((r)[2]), "=r"((r)[3]) : "r"(a))
#define LDSM4T(r, a) \
    asm volatile("ldmatrix.sync.aligned.m8n8.x4.trans.shared.b16 {%0,%1,%2,%3}, [%4];" \
        : "=r"((r)[0]), "=r"((r)[1]), "=r"((r)[2]), "=r"((r)[3]) : "r"(a))

#define MMA16816(d, a, b0, b1) \
    asm volatile("mma.sync.aligned.m16n8k16.row.col.f32.f16.f16.f32 " \
        "{%0,%1,%2,%3}, {%4,%5,%6,%7}, {%8,%9}, {%0,%1,%2,%3};" \
        : "+f"((d)[0]), "+f"((d)[1]), "+f"((d)[2]), "+f"((d)[3]) \
        : "r"((a)[0]), "r"((a)[1]), "r"((a)[2]), "r"((a)[3]), "r"(b0), "r"(b1))

__device__ __forceinline__ uint32_t packh2(float a, float b) {
    __half2 h = __floats2half2_rn(a, b);
    return *(uint32_t*)&h;
}

// ===================== scratch ==============================================
__device__ float g_x1 [(size_t)NTOK * BDIM];
__device__ unsigned short g_qkvh[(size_t)NTOK * 3 * BDIM];
__device__ unsigned short g_xnh[(size_t)NTOK * BDIM];
__device__ unsigned short g_ath[(size_t)NTOK * BDIM];
__device__ unsigned short g_hh [(size_t)NTOK * HID];
__device__ unsigned short g_wqkvh[(size_t)3 * BDIM * BDIM];
__device__ unsigned short g_woh[(size_t)BDIM * BDIM];
__device__ unsigned short g_wuph[(size_t)HID * BDIM];
__device__ unsigned short g_wgh [(size_t)HID * BDIM];
__device__ unsigned short g_wdh [(size_t)BDIM * HID];

// ===================== fused weight convert fp32 -> fp16 ====================
// segments (in 4-elem units): qkv 786432 | o 262144 | up 1048576 | gate 1048576 | down 1048576
#define CV0 786432
#define CV1 (CV0 + 262144)
#define CV2 (CV1 + 1048576)
#define CV3 (CV2 + 1048576)
#define CV4 (CV3 + 1048576)

__global__ void cvt_all(const float* __restrict__ wq, const float* __restrict__ wo,
                        const float* __restrict__ wu, const float* __restrict__ wg,
                        const float* __restrict__ wd,
                        __half* __restrict__ oq, __half* __restrict__ oo,
                        __half* __restrict__ ou, __half* __restrict__ og,
                        __half* __restrict__ od)
{
    int u = blockIdx.x * blockDim.x + threadIdx.x;
    if (u >= CV4) return;
    const float* in; __half* out; int base;
    if      (u < CV0) { in = wq; out = oq; base = 0;   }
    else if (u < CV1) { in = wo; out = oo; base = CV0; }
    else if (u < CV2) { in = wu; out = ou; base = CV1; }
    else if (u < CV3) { in = wg; out = og; base = CV2; }
    else              { in = wd; out = od; base = CV3; }
    int i4 = (u - base) * 4;
    float4 v = *(const float4*)(in + i4);
    *(__half2*)(out + i4)     = __floats2half2_rn(v.x, v.y);
    *(__half2*)(out + i4 + 2) = __floats2half2_rn(v.z, v.w);
}

// ===================== rmsnorm -> fp16 ======================================
__global__ void rmsnorm_h(const float* __restrict__ x,
                          const float* __restrict__ scale,
                          __half* __restrict__ ohi)
{
    int row = blockIdx.x;
    float4 v = ((const float4*)(x + (size_t)row * BDIM))[threadIdx.x];
    float ss = v.x * v.x + v.y * v.y + v.z * v.z + v.w * v.w;
    #pragma unroll
    for (int o = 16; o > 0; o >>= 1) ss += __shfl_xor_sync(0xffffffffu, ss, o);
    __shared__ float ws[8];
    if ((threadIdx.x & 31) == 0) ws[threadIdx.x >> 5] = ss;
    __syncthreads();
    float tot = ws[0] + ws[1] + ws[2] + ws[3] + ws[4] + ws[5] + ws[6] + ws[7];
    float inv = 1.0f / sqrtf(tot * (1.0f / BDIM) + EPSV);
    float4 sc = ((const float4*)scale)[threadIdx.x];
    size_t off = (size_t)row * BDIM + threadIdx.x * 4;
    *(__half2*)(ohi + off)     = __floats2half2_rn(v.x * inv * sc.x, v.y * inv * sc.y);
    *(__half2*)(ohi + off + 2) = __floats2half2_rn(v.z * inv * sc.z, v.w * inv * sc.w);
}

// ===================== HMMA fp16 GEMM =======================================
// C[M,N] = Ah[M,K] * Bh[N,K]^T ; fp32 accum.
// EPI 1: C(fp32) = acc + R ; EPI 3: O1(fp16) = acc
#define BM 128
#define BN 128
#define BKE 32
#define LDSB 80
#define BUF_B (BM * LDSB)           // 10240
#define STG_B (2 * BUF_B)           // 20480
#define NSTAGE 5
#define GEMM_SMEM (NSTAGE * STG_B)  // 102400

template<int EPI>
__global__ __launch_bounds__(256, 1)
void gemm_hmma(const __half* __restrict__ Ah, const __half* __restrict__ Bh,
               float* __restrict__ C, const float* __restrict__ R,
               __half* __restrict__ O1,
               int M, int N, int K)
{
    extern __shared__ char smem[];
    const uint32_t sb = smem_u32(smem);

    const int tid  = threadIdx.x;
    const int lane = tid & 31;
    const int wid  = tid >> 5;
    const int wm   = wid & 3;
    const int wn   = wid >> 2;
    const int bm = blockIdx.y * BM, bn = blockIdx.x * BN;

    const __half* gptr[2][2];
    uint32_t      sptr[2][2];
    {
        const __half* gsrc[2] = {Ah, Bh};
        #pragma unroll
        for (int q = 0; q < 2; q++) {
            int rbase = (q == 0) ? bm : bn;
            #pragma unroll
            for (int j = 0; j < 2; j++) {
                int idx = tid * 2 + j;
                int row = idx >> 2, kc = idx & 3;
                gptr[q][j] = gsrc[q] + (size_t)(rbase + row) * K + kc * 8;
                sptr[q][j] = sb + q * BUF_B + row * LDSB + kc * 16;
            }
        }
    }

    const int nch = K / BKE;

    #pragma unroll
    for (int s = 0; s < NSTAGE; s++) {
        #pragma unroll
        for (int q = 0; q < 2; q++)
            #pragma unroll
            for (int j = 0; j < 2; j++)
                CP_ASYNC16(sptr[q][j] + s * STG_B, gptr[q][j] + s * BKE);
        CP_COMMIT();
    }

    const uint32_t pA = sb + (wm * 32 + (lane & 15)) * LDSB + ((lane >> 4) * 8) * 2;
    const int b_n = (lane & 7) + ((lane >> 4) & 1) * 8;
    const int b_k = ((lane >> 3) & 1) * 8;
    const uint32_t pB = sb + BUF_B + (wn * 64 + b_n) * LDSB + b_k * 2;

    float acc[2][8][4];
    #pragma unroll
    for (int i = 0; i < 2; i++)
        #pragma unroll
        for (int j = 0; j < 8; j++)
            #pragma unroll
            for (int r = 0; r < 4; r++) acc[i][j][r] = 0.0f;

    for (int c = 0; c < nch; c++) {
        CP_WAIT4();
        __syncthreads();
        const uint32_t so = (c % NSTAGE) * STG_B;

        #pragma unroll
        for (int ks = 0; ks < 2; ks++) {
            uint32_t ah[2][4], bh[4][4];
            #pragma unroll
            for (int i = 0; i < 2; i++)
                LDSM4(ah[i], pA + so + i * (16 * LDSB) + ks * 32);
            #pragma unroll
            for (int j2 = 0; j2 < 4; j2++)
                LDSM4(bh[j2], pB + so + j2 * (16 * LDSB) + ks * 32);
            #pragma unroll
            for (int i = 0; i < 2; i++)
                #pragma unroll
                for (int j = 0; j < 8; j++) {
                    const int j2 = j >> 1, hh = (j & 1) * 2;
                    MMA16816(acc[i][j], ah[i], bh[j2][hh], bh[j2][hh + 1]);
                }
        }
        __syncthreads();

        const int cn = c + NSTAGE;
        if (cn < nch) {
            #pragma unroll
            for (int q = 0; q < 2; q++)
                #pragma unroll
                for (int j = 0; j < 2; j++)
                    CP_ASYNC16(sptr[q][j] + so, gptr[q][j] + cn * BKE);
        }
        CP_COMMIT();
    }

    const int g  = lane >> 2;
    const int c2 = (lane & 3) * 2;
    #pragma unroll
    for (int i = 0; i < 2; i++) {
        #pragma unroll
        for (int j = 0; j < 8; j++) {
            const int col = bn + wn * 64 + j * 8 + c2;
            const int r0 = bm + wm * 32 + i * 16 + g;
            #pragma unroll
            for (int hrow = 0; hrow < 2; hrow++) {
                const int row = r0 + hrow * 8;
                const size_t base = (size_t)row * N + col;
                float v0 = acc[i][j][hrow * 2 + 0];
                float v1 = acc[i][j][hrow * 2 + 1];
                if (EPI == 1) {
                    float2 rv = *(const float2*)(R + base);
                    *(float2*)(C + base) = make_float2(v0 + rv.x, v1 + rv.y);
                } else {
                    *(__half2*)(O1 + base) = __floats2half2_rn(v0, v1);
                }
            }
        }
    }
}

// ===================== fused up+gate GEMM ===================================
// hh[M,N] = (A*Wup^T) * silu(A*Wgate^T), fp16 out. N = HID.
#define UG_STG (3 * BUF_B)            // A|Bu|Bg = 30720
#define UG_NSTAGE 4
#define UG_SMEM (UG_NSTAGE * UG_STG)  // 122880

__global__ __launch_bounds__(256, 1)
void gemm_upgate(const __half* __restrict__ Ah, const __half* __restrict__ Bu,
                 const __half* __restrict__ Bg, __half* __restrict__ O1,
                 int M, int N, int K)
{
    extern __shared__ char smem[];
    const uint32_t sb = smem_u32(smem);

    const int tid  = threadIdx.x;
    const int lane = tid & 31;
    const int wid  = tid >> 5;
    const int wm   = wid & 3;
    const int wn   = wid >> 2;
    const int bm = blockIdx.y * BM, bn = blockIdx.x * BN;

    const __half* gptr[3][2];
    uint32_t      sptr[3][2];
    {
        const __half* gsrc[3] = {Ah, Bu, Bg};
        #pragma unroll
        for (int q = 0; q < 3; q++) {
            int rbase = (q == 0) ? bm : bn;
            #pragma unroll
            for (int j = 0; j < 2; j++) {
                int idx = tid * 2 + j;
                int row = idx >> 2, kc = idx & 3;
                gptr[q][j] = gsrc[q] + (size_t)(rbase + row) * K + kc * 8;
                sptr[q][j] = sb + q * BUF_B + row * LDSB + kc * 16;
            }
        }
    }

    const int nch = K / BKE;

    #pragma unroll
    for (int s = 0; s < UG_NSTAGE; s++) {
        #pragma unroll
        for (int q = 0; q < 3; q++)
            #pragma unroll
            for (int j = 0; j < 2; j++)
                CP_ASYNC16(sptr[q][j] + s * UG_STG, gptr[q][j] + s * BKE);
        CP_COMMIT();
    }

    const uint32_t pA = sb + (wm * 32 + (lane & 15)) * LDSB + ((lane >> 4) * 8) * 2;
    const int b_n = (lane & 7) + ((lane >> 4) & 1) * 8;
    const int b_k = ((lane >> 3) & 1) * 8;
    const uint32_t pBu = sb + 1 * BUF_B + (wn * 64 + b_n) * LDSB + b_k * 2;
    const uint32_t pBg = sb + 2 * BUF_B + (wn * 64 + b_n) * LDSB + b_k * 2;

    float au[2][8][4], ag[2][8][4];
    #pragma unroll
    for (int i = 0; i < 2; i++)
        #pragma unroll
        for (int j = 0; j < 8; j++)
            #pragma unroll
            for (int r = 0; r < 4; r++) { au[i][j][r] = 0.0f; ag[i][j][r] = 0.0f; }

    for (int c = 0; c < nch; c++) {
        CP_WAIT3();
        __syncthreads();
        const uint32_t so = (c % UG_NSTAGE) * UG_STG;

        #pragma unroll
        for (int ks = 0; ks < 2; ks++) {
            uint32_t ah[2][4], bh[4][4];
            #pragma unroll
            for (int i = 0; i < 2; i++)
                LDSM4(ah[i], pA + so + i * (16 * LDSB) + ks * 32);
            // up
            #pragma unroll
            for (int j2 = 0; j2 < 4; j2++)
                LDSM4(bh[j2], pBu + so + j2 * (16 * LDSB) + ks * 32);
            #pragma unroll
            for (int i = 0; i < 2; i++)
                #pragma unroll
                for (int j = 0; j < 8; j++) {
                    const int j2 = j >> 1, hh = (j & 1) * 2;
                    MMA16816(au[i][j], ah[i], bh[j2][hh], bh[j2][hh + 1]);
                }
            // gate
            #pragma unroll
            for (int j2 = 0; j2 < 4; j2++)
                LDSM4(bh[j2], pBg + so + j2 * (16 * LDSB) + ks * 32);
            #pragma unroll
            for (int i = 0; i < 2; i++)
                #pragma unroll
                for (int j = 0; j < 8; j++) {
                    const int j2 = j >> 1, hh = (j & 1) * 2;
                    MMA16816(ag[i][j], ah[i], bh[j2][hh], bh[j2][hh + 1]);
                }
        }
        __syncthreads();

        const int cn = c + UG_NSTAGE;
        if (cn < nch) {
            #pragma unroll
            for (int q = 0; q < 3; q++)
                #pragma unroll
                for (int j = 0; j < 2; j++)
                    CP_ASYNC16(sptr[q][j] + so, gptr[q][j] + cn * BKE);
        }
        CP_COMMIT();
    }

    const int g  = lane >> 2;
    const int c2 = (lane & 3) * 2;
    #pragma unroll
    for (int i = 0; i < 2; i++) {
        #pragma unroll
        for (int j = 0; j < 8; j++) {
            const int col = bn + wn * 64 + j * 8 + c2;
            const int r0 = bm + wm * 32 + i * 16 + g;
            #pragma unroll
            for (int hrow = 0; hrow < 2; hrow++) {
                const int row = r0 + hrow * 8;
                const size_t base = (size_t)row * N + col;
                float u0 = au[i][j][hrow * 2 + 0], u1 = au[i][j][hrow * 2 + 1];
                float g0 = ag[i][j][hrow * 2 + 0], g1 = ag[i][j][hrow * 2 + 1];
                float s0 = u0 * (g0 / (1.0f + __expf(-g0)));
                float s1 = u1 * (g1 / (1.0f + __expf(-g1)));
                *(__half2*)(O1 + base) = __floats2half2_rn(s0, s1);
            }
        }
    }
}

// ===================== fp16 HMMA flash attention (128 q-rows) ==============
#define AST 72

__global__ __launch_bounds__(256)
void flash_attn_h(const __half* __restrict__ qkvh, __half* __restrict__ outh)
{
    __shared__ __half Qs[128][AST];
    __shared__ __half Ks[64][AST];
    __shared__ __half Vs[64][AST];

    const int qb = blockIdx.x, hd = blockIdx.y, b = blockIdx.z;
    const int q0 = qb * 128;
    const int tid = threadIdx.x, lane = tid & 31, wid = tid >> 5;
    const int ld = 3 * BDIM;
    const int g = lane >> 2, c2 = lane & 3;

    const __half* qbase = qkvh + ((size_t)(b * SEQ + q0)) * ld + hd * DHEAD;
    #pragma unroll
    for (int i = 0; i < 4; i++) {
        int idx = tid + i * 256;            // 1024 8-half chunks
        int r = idx >> 3, c8 = (idx & 7) * 8;
        *(uint4*)&Qs[r][c8] = *(const uint4*)(qbase + (size_t)r * ld + c8);
    }

    const __half* kbase = qkvh + (size_t)(b * SEQ) * ld + BDIM     + hd * DHEAD;
    const __half* vbase = qkvh + (size_t)(b * SEQ) * ld + 2 * BDIM + hd * DHEAD;

    float o[8][4];
    #pragma unroll
    for (int j = 0; j < 8; j++)
        #pragma unroll
        for (int r = 0; r < 4; r++) o[j][r] = 0.0f;
    float mrow[2] = {-1e30f, -1e30f}, lsum[2] = {0.0f, 0.0f};

    const uint32_t qaddr = smem_u32(&Qs[wid * 16 + (lane & 15)][(lane >> 4) * 8]);
    const uint32_t kaddr = smem_u32(&Ks[(lane & 7) + ((lane >> 4) & 1) * 8]
                                       [((lane >> 3) & 1) * 8]);
    const uint32_t vaddr = smem_u32(&Vs[(lane & 7) + ((lane >> 3) & 1) * 8]
                                       [((lane >> 4) & 1) * 8]);

    const int ntiles = 2 * qb + 2;
    const int qrow0 = q0 + wid * 16 + g;        // rows qrow0, qrow0+8
    const int wmax  = q0 + wid * 16 + 15;       // last q-row of this warp

    for (int t = 0; t < ntiles; t++) {
        const int kv0 = t * 64;
        __syncthreads();
        #pragma unroll
        for (int i = 0; i < 2; i++) {
            int idx = tid + i * 256;            // 512 8-half chunks
            int r = idx >> 3, c8 = (idx & 7) * 8;
            *(uint4*)&Ks[r][c8] = *(const uint4*)(kbase + (size_t)(kv0 + r) * ld + c8);
            *(uint4*)&Vs[r][c8] = *(const uint4*)(vbase + (size_t)(kv0 + r) * ld + c8);
        }
        __syncthreads();

        if (kv0 > wmax) continue;               // fully-masked tile for this warp

        // ---- S = Q K^T
        float s[8][4];
        #pragma unroll
        for (int j = 0; j < 8; j++)
            #pragma unroll
            for (int r = 0; r < 4; r++) s[j][r] = 0.0f;
        #pragma unroll
        for (int kk = 0; kk < 4; kk++) {
            uint32_t qa[4];
            LDSM4(qa, qaddr + kk * 32);
            #pragma unroll
            for (int j2 = 0; j2 < 4; j2++) {
                uint32_t kb[4];
                LDSM4(kb, kaddr + j2 * (16 * AST * 2) + kk * 32);
                MMA16816(s[2 * j2],     qa, kb[0], kb[1]);
                MMA16816(s[2 * j2 + 1], qa, kb[2], kb[3]);
            }
        }

        // ---- scale + causal mask (only near-diagonal tiles can be partial)
        const float scale = 0.125f;
        if (t >= ntiles - 2) {
            #pragma unroll
            for (int j = 0; j < 8; j++) {
                int col = kv0 + j * 8 + c2 * 2;
                s[j][0] = (col     > qrow0)     ? -1e30f : s[j][0] * scale;
                s[j][1] = (col + 1 > qrow0)     ? -1e30f : s[j][1] * scale;
                s[j][2] = (col     > qrow0 + 8) ? -1e30f : s[j][2] * scale;
                s[j][3] = (col + 1 > qrow0 + 8) ? -1e30f : s[j][3] * scale;
            }
        } else {
            #pragma unroll
            for (int j = 0; j < 8; j++)
                #pragma unroll
                for (int r = 0; r < 4; r++) s[j][r] *= scale;
        }

        // ---- online softmax
        float mx0 = -1e30f, mx1 = -1e30f;
        #pragma unroll
        for (int j = 0; j < 8; j++) {
            mx0 = fmaxf(mx0, fmaxf(s[j][0], s[j][1]));
            mx1 = fmaxf(mx1, fmaxf(s[j][2], s[j][3]));
        }
        mx0 = fmaxf(mx0, __shfl_xor_sync(0xffffffffu, mx0, 1));
        mx0 = fmaxf(mx0, __shfl_xor_sync(0xffffffffu, mx0, 2));
        mx1 = fmaxf(mx1, __shfl_xor_sync(0xffffffffu, mx1, 1));
        mx1 = fmaxf(mx1, __shfl_xor_sync(0xffffffffu, mx1, 2));
        float mn0 = fmaxf(mrow[0], mx0), mn1 = fmaxf(mrow[1], mx1);
        float fac0 = __expf(mrow[0] - mn0), fac1 = __expf(mrow[1] - mn1);
        float ps0 = 0.0f, ps1 = 0.0f;
        #pragma unroll
        for (int j = 0; j < 8; j++) {
            s[j][0] = __expf(s[j][0] - mn0);
            s[j][1] = __expf(s[j][1] - mn0);
            s[j][2] = __expf(s[j][2] - mn1);
            s[j][3] = __expf(s[j][3] - mn1);
            ps0 += s[j][0] + s[j][1];
            ps1 += s[j][2] + s[j][3];
        }
        ps0 += __shfl_xor_sync(0xffffffffu, ps0, 1);
        ps0 += __shfl_xor_sync(0xffffffffu, ps0, 2);
        ps1 += __shfl_xor_sync(0xffffffffu, ps1, 1);
        ps1 += __shfl_xor_sync(0xffffffffu, ps1, 2);
        lsum[0] = lsum[0] * fac0 + ps0;  mrow[0] = mn0;
        lsum[1] = lsum[1] * fac1 + ps1;  mrow[1] = mn1;
        #pragma unroll
        for (int j = 0; j < 8; j++) {
            o[j][0] *= fac0; o[j][1] *= fac0;
            o[j][2] *= fac1; o[j][3] *= fac1;
        }

        // ---- P fragments
        uint32_t pa[4][4];
        #pragma unroll
        for (int kk = 0; kk < 4; kk++) {
            pa[kk][0] = packh2(s[2 * kk][0],     s[2 * kk][1]);
            pa[kk][1] = packh2(s[2 * kk][2],     s[2 * kk][3]);
            pa[kk][2] = packh2(s[2 * kk + 1][0], s[2 * kk + 1][1]);
            pa[kk][3] = packh2(s[2 * kk + 1][2], s[2 * kk + 1][3]);
        }

        // ---- O += P V
        #pragma unroll
        for (int j2 = 0; j2 < 4; j2++) {
            #pragma unroll
            for (int kk = 0; kk < 4; kk++) {
                uint32_t vb[4];
                LDSM4T(vb, vaddr + kk * (16 * AST * 2) + j2 * 32);
                MMA16816(o[2 * j2],     pa[kk], vb[0], vb[1]);
                MMA16816(o[2 * j2 + 1], pa[kk], vb[2], vb[3]);
            }
        }
    }

    float inv0 = 1.0f / lsum[0], inv1 = 1.0f / lsum[1];
    const size_t rbase0 = ((size_t)(b * SEQ) + qrow0) * BDIM + hd * DHEAD;
    const size_t rbase1 = rbase0 + (size_t)8 * BDIM;
    #pragma unroll
    for (int j = 0; j < 8; j++) {
        int col = j * 8 + c2 * 2;
        *(__half2*)(outh + rbase0 + col) = __floats2half2_rn(o[j][0] * inv0, o[j][1] * inv0);
        *(__half2*)(outh + rbase1 + col) = __floats2half2_rn(o[j][2] * inv1, o[j][3] * inv1);
    }
}

// ===================== launch ==============================================
extern "C" void kernel_launch(void* const* d_in, const int* in_sizes, int n_in,
                              void* d_out, int out_size)
{
    const float* x      = (const float*)d_in[0];
    const float* w_qkv  = (const float*)d_in[1];
    const float* w_o    = (const float*)d_in[2];
    const float* w_up   = (const float*)d_in[3];
    const float* w_gate = (const float*)d_in[4];
    const float* w_down = (const float*)d_in[5];
    const float* scale1 = (const float*)d_in[6];
    const float* scale2 = (const float*)d_in[7];
    float* out = (float*)d_out;

    float *x1;
    __half *qkvh, *xnh, *ath, *hh;
    __half *wqkvh, *woh, *wuph, *wgh, *wdh;
    cudaGetSymbolAddress((void**)&x1,   g_x1);
    cudaGetSymbolAddress((void**)&qkvh, g_qkvh);
    cudaGetSymbolAddress((void**)&xnh, g_xnh);
    cudaGetSymbolAddress((void**)&ath, g_ath);
    cudaGetSymbolAddress((void**)&hh,  g_hh);
    cudaGetSymbolAddress((void**)&wqkvh, g_wqkvh);
    cudaGetSymbolAddress((void**)&woh, g_woh);
    cudaGetSymbolAddress((void**)&wuph, g_wuph);
    cudaGetSymbolAddress((void**)&wgh, g_wgh);
    cudaGetSymbolAddress((void**)&wdh, g_wdh);

    cudaFuncSetAttribute(gemm_hmma<1>,
                         cudaFuncAttributeMaxDynamicSharedMemorySize, GEMM_SMEM);
    cudaFuncSetAttribute(gemm_hmma<3>,
                         cudaFuncAttributeMaxDynamicSharedMemorySize, GEMM_SMEM);
    cudaFuncSetAttribute(gemm_upgate,
                         cudaFuncAttributeMaxDynamicSharedMemorySize, UG_SMEM);

    // 0. all weight converts in one launch
    cvt_all<<<(CV4 + 255) / 256, 256>>>(w_qkv, w_o, w_up, w_gate, w_down,
                                        wqkvh, woh, wuph, wgh, wdh);

    // 1. xn = rmsnorm(x, scale1) -> fp16
    rmsnorm_h<<<NTOK, 256>>>(x, scale1, xnh);

    // 2. qkvh = fp16(xn @ w_qkv.T)
    {
        dim3 g(3 * BDIM / BN, NTOK / BM);
        gemm_hmma<3><<<g, 256, GEMM_SMEM>>>(xnh, wqkvh, nullptr, nullptr, qkvh,
                                            NTOK, 3 * BDIM, BDIM);
    }

    // 3. attention core -> ath (fp16)
    {
        dim3 g(SEQ / 128, NHEAD, BATCH);
        flash_attn_h<<<g, 256>>>(qkvh, ath);
    }

    // 4. x1 = x + attn @ w_o.T
    {
        dim3 g(BDIM / BN, NTOK / BM);
        gemm_hmma<1><<<g, 256, GEMM_SMEM>>>(ath, woh, x1, x, nullptr,
                                            NTOK, BDIM, BDIM);
    }

    // 5. xn = rmsnorm(x1, scale2) -> fp16
    rmsnorm_h<<<NTOK, 256>>>(x1, scale2, xnh);

    // 6+7. hh = (xn @ w_up.T) * silu(xn @ w_gate.T)  (fused, fp16)
    {
        dim3 g(HID / BN, NTOK / BM);
        gemm_upgate<<<g, 256, UG_SMEM>>>(xnh, wuph, wgh, hh, NTOK, HID, BDIM);
    }

    // 8. out = x1 + hh @ w_down.T
    {
        dim3 g(BDIM / BN, NTOK / BM);
        gemm_hmma<1><<<g, 256, GEMM_SMEM>>>(hh, wdh, out, x1, nullptr,
                                            NTOK, BDIM, HID);
    }
}

// round 7
// speedup vs baseline: 5.8245x; 1.0306x over previous
#include <cuda_runtime.h>
#include <cuda_fp16.h>
#include <cstdint>
#include <math.h>

#define BDIM   1024
#define NHEAD  16
#define DHEAD  64
#define SEQ    2048
#define BATCH  2
#define NTOK   (BATCH * SEQ)      // 4096
#define HID    (4 * BDIM)         // 4096
#define EPSV   1e-6f

// ===================== helpers =============================================
__device__ __forceinline__ uint32_t smem_u32(const void* p) {
    uint32_t a;
    asm("{ .reg .u64 t; cvta.to.shared.u64 t, %1; cvt.u32.u64 %0, t; }"
        : "=r"(a) : "l"(p));
    return a;
}

#define CP_ASYNC16(s, g) \
    asm volatile("cp.async.cg.shared.global [%0], [%1], 16;" :: "r"(s), "l"(g))
#define CP_COMMIT()  asm volatile("cp.async.commit_group;" ::: "memory")
#define CP_WAIT1()   asm volatile("cp.async.wait_group 1;" ::: "memory")
#define CP_WAIT2()   asm volatile("cp.async.wait_group 2;" ::: "memory")

#define LDSM4(r, a) \
    asm volatile("ldmatrix.sync.aligned.m8n8.x4.shared.b16 {%0,%1,%2,%3}, [%4];" \
        : "=r"((r)[0]), "=r"((r)[1]), "=r"((r)[2]), "=r"((r)[3]) : "r"(a))
#define LDSM4T(r, a) \
    asm volatile("ldmatrix.sync.aligned.m8n8.x4.trans.shared.b16 {%0,%1,%2,%3}, [%4];" \
        : "=r"((r)[0]), "=r"((r)[1]), "=r"((r)[2]), "=r"((r)[3]) : "r"(a))

#define MMA16816(d, a, b0, b1) \
    asm volatile("mma.sync.aligned.m16n8k16.row.col.f32.f16.f16.f32 " \
        "{%0,%1,%2,%3}, {%4,%5,%6,%7}, {%8,%9}, {%0,%1,%2,%3};" \
        : "+f"((d)[0]), "+f"((d)[1]), "+f"((d)[2]), "+f"((d)[3]) \
        : "r"((a)[0]), "r"((a)[1]), "r"((a)[2]), "r"((a)[3]), "r"(b0), "r"(b1))

__device__ __forceinline__ uint32_t packh2(float a, float b) {
    __half2 h = __floats2half2_rn(a, b);
    return *(uint32_t*)&h;
}

// ===================== scratch ==============================================
__device__ float g_x1 [(size_t)NTOK * BDIM];
__device__ unsigned short g_qkvh[(size_t)NTOK * 3 * BDIM];
__device__ unsigned short g_xnh[(size_t)NTOK * BDIM];
__device__ unsigned short g_ath[(size_t)NTOK * BDIM];
__device__ unsigned short g_hh [(size_t)NTOK * HID];
__device__ unsigned short g_wqkvh[(size_t)3 * BDIM * BDIM];
__device__ unsigned short g_woh[(size_t)BDIM * BDIM];
__device__ unsigned short g_wuph[(size_t)HID * BDIM];
__device__ unsigned short g_wgh [(size_t)HID * BDIM];
__device__ unsigned short g_wdh [(size_t)BDIM * HID];

// ===================== fused weight convert fp32 -> fp16 ====================
#define CV0 786432
#define CV1 (CV0 + 262144)
#define CV2 (CV1 + 1048576)
#define CV3 (CV2 + 1048576)
#define CV4 (CV3 + 1048576)

__global__ void cvt_all(const float* __restrict__ wq, const float* __restrict__ wo,
                        const float* __restrict__ wu, const float* __restrict__ wg,
                        const float* __restrict__ wd,
                        __half* __restrict__ oq, __half* __restrict__ oo,
                        __half* __restrict__ ou, __half* __restrict__ og,
                        __half* __restrict__ od)
{
    int u = blockIdx.x * blockDim.x + threadIdx.x;
    if (u >= CV4) return;
    const float* in; __half* out; int base;
    if      (u < CV0) { in = wq; out = oq; base = 0;   }
    else if (u < CV1) { in = wo; out = oo; base = CV0; }
    else if (u < CV2) { in = wu; out = ou; base = CV1; }
    else if (u < CV3) { in = wg; out = og; base = CV2; }
    else              { in = wd; out = od; base = CV3; }
    int i4 = (u - base) * 4;
    float4 v = *(const float4*)(in + i4);
    *(__half2*)(out + i4)     = __floats2half2_rn(v.x, v.y);
    *(__half2*)(out + i4 + 2) = __floats2half2_rn(v.z, v.w);
}

// ===================== rmsnorm -> fp16 ======================================
__global__ void rmsnorm_h(const float* __restrict__ x,
                          const float* __restrict__ scale,
                          __half* __restrict__ ohi)
{
    int row = blockIdx.x;
    float4 v = ((const float4*)(x + (size_t)row * BDIM))[threadIdx.x];
    float ss = v.x * v.x + v.y * v.y + v.z * v.z + v.w * v.w;
    #pragma unroll
    for (int o = 16; o > 0; o >>= 1) ss += __shfl_xor_sync(0xffffffffu, ss, o);
    __shared__ float ws[8];
    if ((threadIdx.x & 31) == 0) ws[threadIdx.x >> 5] = ss;
    __syncthreads();
    float tot = ws[0] + ws[1] + ws[2] + ws[3] + ws[4] + ws[5] + ws[6] + ws[7];
    float inv = 1.0f / sqrtf(tot * (1.0f / BDIM) + EPSV);
    float4 sc = ((const float4*)scale)[threadIdx.x];
    size_t off = (size_t)row * BDIM + threadIdx.x * 4;
    *(__half2*)(ohi + off)     = __floats2half2_rn(v.x * inv * sc.x, v.y * inv * sc.y);
    *(__half2*)(ohi + off + 2) = __floats2half2_rn(v.z * inv * sc.z, v.w * inv * sc.w);
}

// ===================== HMMA fp16 GEMM (2 CTAs/SM, 3-stage) ==================
// C[M,N] = Ah[M,K] * Bh[N,K]^T ; fp32 accum.
// EPI 1: C(fp32) = acc + R ; EPI 3: O1(fp16) = acc
#define BM 128
#define BN 128
#define BKE 32
#define LDSB 80
#define BUF_B (BM * LDSB)           // 10240
#define STG_B (2 * BUF_B)           // 20480
#define NSTAGE 3
#define GEMM_SMEM (NSTAGE * STG_B)  // 61440

template<int EPI>
__global__ __launch_bounds__(256, 2)
void gemm_hmma(const __half* __restrict__ Ah, const __half* __restrict__ Bh,
               float* __restrict__ C, const float* __restrict__ R,
               __half* __restrict__ O1,
               int M, int N, int K)
{
    extern __shared__ char smem[];
    const uint32_t sb = smem_u32(smem);

    const int tid  = threadIdx.x;
    const int lane = tid & 31;
    const int wid  = tid >> 5;
    const int wm   = wid & 3;
    const int wn   = wid >> 2;
    const int bm = blockIdx.y * BM, bn = blockIdx.x * BN;

    const __half* gptr[2][2];
    uint32_t      sptr[2][2];
    {
        const __half* gsrc[2] = {Ah, Bh};
        #pragma unroll
        for (int q = 0; q < 2; q++) {
            int rbase = (q == 0) ? bm : bn;
            #pragma unroll
            for (int j = 0; j < 2; j++) {
                int idx = tid * 2 + j;
                int row = idx >> 2, kc = idx & 3;
                gptr[q][j] = gsrc[q] + (size_t)(rbase + row) * K + kc * 8;
                sptr[q][j] = sb + q * BUF_B + row * LDSB + kc * 16;
            }
        }
    }

    const int nch = K / BKE;

    // prologue: stages 0..NSTAGE-2
    #pragma unroll
    for (int s = 0; s < NSTAGE - 1; s++) {
        #pragma unroll
        for (int q = 0; q < 2; q++)
            #pragma unroll
            for (int j = 0; j < 2; j++)
                CP_ASYNC16(sptr[q][j] + s * STG_B, gptr[q][j] + s * BKE);
        CP_COMMIT();
    }

    const uint32_t pA = sb + (wm * 32 + (lane & 15)) * LDSB + ((lane >> 4) * 8) * 2;
    const int b_n = (lane & 7) + ((lane >> 4) & 1) * 8;
    const int b_k = ((lane >> 3) & 1) * 8;
    const uint32_t pB = sb + BUF_B + (wn * 64 + b_n) * LDSB + b_k * 2;

    float acc[2][8][4];
    #pragma unroll
    for (int i = 0; i < 2; i++)
        #pragma unroll
        for (int j = 0; j < 8; j++)
            #pragma unroll
            for (int r = 0; r < 4; r++) acc[i][j][r] = 0.0f;

    for (int c = 0; c < nch; c++) {
        CP_WAIT1();                    // stage c complete
        __syncthreads();               // all warps done reading stage c-1

        const int cn = c + NSTAGE - 1; // prefetch into freed stage
        if (cn < nch) {
            const uint32_t sw = (cn % NSTAGE) * STG_B;
            #pragma unroll
            for (int q = 0; q < 2; q++)
                #pragma unroll
                for (int j = 0; j < 2; j++)
                    CP_ASYNC16(sptr[q][j] + sw, gptr[q][j] + cn * BKE);
        }
        CP_COMMIT();

        const uint32_t so = (c % NSTAGE) * STG_B;
        #pragma unroll
        for (int ks = 0; ks < 2; ks++) {
            uint32_t ah[2][4], bh[4][4];
            #pragma unroll
            for (int i = 0; i < 2; i++)
                LDSM4(ah[i], pA + so + i * (16 * LDSB) + ks * 32);
            #pragma unroll
            for (int j2 = 0; j2 < 4; j2++)
                LDSM4(bh[j2], pB + so + j2 * (16 * LDSB) + ks * 32);
            #pragma unroll
            for (int i = 0; i < 2; i++)
                #pragma unroll
                for (int j = 0; j < 8; j++) {
                    const int j2 = j >> 1, hh = (j & 1) * 2;
                    MMA16816(acc[i][j], ah[i], bh[j2][hh], bh[j2][hh + 1]);
                }
        }
    }

    const int g  = lane >> 2;
    const int c2 = (lane & 3) * 2;
    #pragma unroll
    for (int i = 0; i < 2; i++) {
        #pragma unroll
        for (int j = 0; j < 8; j++) {
            const int col = bn + wn * 64 + j * 8 + c2;
            const int r0 = bm + wm * 32 + i * 16 + g;
            #pragma unroll
            for (int hrow = 0; hrow < 2; hrow++) {
                const int row = r0 + hrow * 8;
                const size_t base = (size_t)row * N + col;
                float v0 = acc[i][j][hrow * 2 + 0];
                float v1 = acc[i][j][hrow * 2 + 1];
                if (EPI == 1) {
                    float2 rv = *(const float2*)(R + base);
                    *(float2*)(C + base) = make_float2(v0 + rv.x, v1 + rv.y);
                } else {
                    *(__half2*)(O1 + base) = __floats2half2_rn(v0, v1);
                }
            }
        }
    }
}

// ===================== fused up+gate GEMM (4-stage, 1 CTA) ==================
#define UG_STG (3 * BUF_B)            // 30720
#define UG_NSTAGE 4
#define UG_SMEM (UG_NSTAGE * UG_STG)  // 122880

__global__ __launch_bounds__(256, 1)
void gemm_upgate(const __half* __restrict__ Ah, const __half* __restrict__ Bu,
                 const __half* __restrict__ Bg, __half* __restrict__ O1,
                 int M, int N, int K)
{
    extern __shared__ char smem[];
    const uint32_t sb = smem_u32(smem);

    const int tid  = threadIdx.x;
    const int lane = tid & 31;
    const int wid  = tid >> 5;
    const int wm   = wid & 3;
    const int wn   = wid >> 2;
    const int bm = blockIdx.y * BM, bn = blockIdx.x * BN;

    const __half* gptr[3][2];
    uint32_t      sptr[3][2];
    {
        const __half* gsrc[3] = {Ah, Bu, Bg};
        #pragma unroll
        for (int q = 0; q < 3; q++) {
            int rbase = (q == 0) ? bm : bn;
            #pragma unroll
            for (int j = 0; j < 2; j++) {
                int idx = tid * 2 + j;
                int row = idx >> 2, kc = idx & 3;
                gptr[q][j] = gsrc[q] + (size_t)(rbase + row) * K + kc * 8;
                sptr[q][j] = sb + q * BUF_B + row * LDSB + kc * 16;
            }
        }
    }

    const int nch = K / BKE;

    #pragma unroll
    for (int s = 0; s < UG_NSTAGE - 1; s++) {
        #pragma unroll
        for (int q = 0; q < 3; q++)
            #pragma unroll
            for (int j = 0; j < 2; j++)
                CP_ASYNC16(sptr[q][j] + s * UG_STG, gptr[q][j] + s * BKE);
        CP_COMMIT();
    }

    const uint32_t pA = sb + (wm * 32 + (lane & 15)) * LDSB + ((lane >> 4) * 8) * 2;
    const int b_n = (lane & 7) + ((lane >> 4) & 1) * 8;
    const int b_k = ((lane >> 3) & 1) * 8;
    const uint32_t pBu = sb + 1 * BUF_B + (wn * 64 + b_n) * LDSB + b_k * 2;
    const uint32_t pBg = sb + 2 * BUF_B + (wn * 64 + b_n) * LDSB + b_k * 2;

    float au[2][8][4], ag[2][8][4];
    #pragma unroll
    for (int i = 0; i < 2; i++)
        #pragma unroll
        for (int j = 0; j < 8; j++)
            #pragma unroll
            for (int r = 0; r < 4; r++) { au[i][j][r] = 0.0f; ag[i][j][r] = 0.0f; }

    for (int c = 0; c < nch; c++) {
        CP_WAIT2();
        __syncthreads();

        const int cn = c + UG_NSTAGE - 1;
        if (cn < nch) {
            const uint32_t sw = (cn % UG_NSTAGE) * UG_STG;
            #pragma unroll
            for (int q = 0; q < 3; q++)
                #pragma unroll
                for (int j = 0; j < 2; j++)
                    CP_ASYNC16(sptr[q][j] + sw, gptr[q][j] + cn * BKE);
        }
        CP_COMMIT();

        const uint32_t so = (c % UG_NSTAGE) * UG_STG;
        #pragma unroll
        for (int ks = 0; ks < 2; ks++) {
            uint32_t ah[2][4], bh[4][4];
            #pragma unroll
            for (int i = 0; i < 2; i++)
                LDSM4(ah[i], pA + so + i * (16 * LDSB) + ks * 32);
            #pragma unroll
            for (int j2 = 0; j2 < 4; j2++)
                LDSM4(bh[j2], pBu + so + j2 * (16 * LDSB) + ks * 32);
            #pragma unroll
            for (int i = 0; i < 2; i++)
                #pragma unroll
                for (int j = 0; j < 8; j++) {
                    const int j2 = j >> 1, hh = (j & 1) * 2;
                    MMA16816(au[i][j], ah[i], bh[j2][hh], bh[j2][hh + 1]);
                }
            #pragma unroll
            for (int j2 = 0; j2 < 4; j2++)
                LDSM4(bh[j2], pBg + so + j2 * (16 * LDSB) + ks * 32);
            #pragma unroll
            for (int i = 0; i < 2; i++)
                #pragma unroll
                for (int j = 0; j < 8; j++) {
                    const int j2 = j >> 1, hh = (j & 1) * 2;
                    MMA16816(ag[i][j], ah[i], bh[j2][hh], bh[j2][hh + 1]);
                }
        }
    }

    const int g  = lane >> 2;
    const int c2 = (lane & 3) * 2;
    #pragma unroll
    for (int i = 0; i < 2; i++) {
        #pragma unroll
        for (int j = 0; j < 8; j++) {
            const int col = bn + wn * 64 + j * 8 + c2;
            const int r0 = bm + wm * 32 + i * 16 + g;
            #pragma unroll
            for (int hrow = 0; hrow < 2; hrow++) {
                const int row = r0 + hrow * 8;
                const size_t base = (size_t)row * N + col;
                float u0 = au[i][j][hrow * 2 + 0], u1 = au[i][j][hrow * 2 + 1];
                float g0 = ag[i][j][hrow * 2 + 0], g1 = ag[i][j][hrow * 2 + 1];
                float s0 = u0 * (g0 / (1.0f + __expf(-g0)));
                float s1 = u1 * (g1 / (1.0f + __expf(-g1)));
                *(__half2*)(O1 + base) = __floats2half2_rn(s0, s1);
            }
        }
    }
}

// ===================== fp16 HMMA flash attention (128 q-rows) ==============
#define AST 72

__global__ __launch_bounds__(256)
void flash_attn_h(const __half* __restrict__ qkvh, __half* __restrict__ outh)
{
    __shared__ __half Qs[128][AST];
    __shared__ __half Ks[64][AST];
    __shared__ __half Vs[64][AST];

    const int qb = gridDim.x - 1 - blockIdx.x;   // heavy blocks first
    const int hd = blockIdx.y, b = blockIdx.z;
    const int q0 = qb * 128;
    const int tid = threadIdx.x, lane = tid & 31, wid = tid >> 5;
    const int ld = 3 * BDIM;
    const int g = lane >> 2, c2 = lane & 3;

    const __half* qbase = qkvh + ((size_t)(b * SEQ + q0)) * ld + hd * DHEAD;
    #pragma unroll
    for (int i = 0; i < 4; i++) {
        int idx = tid + i * 256;
        int r = idx >> 3, c8 = (idx & 7) * 8;
        *(uint4*)&Qs[r][c8] = *(const uint4*)(qbase + (size_t)r * ld + c8);
    }

    const __half* kbase = qkvh + (size_t)(b * SEQ) * ld + BDIM     + hd * DHEAD;
    const __half* vbase = qkvh + (size_t)(b * SEQ) * ld + 2 * BDIM + hd * DHEAD;

    float o[8][4];
    #pragma unroll
    for (int j = 0; j < 8; j++)
        #pragma unroll
        for (int r = 0; r < 4; r++) o[j][r] = 0.0f;
    float mrow[2] = {-1e30f, -1e30f}, lsum[2] = {0.0f, 0.0f};

    const uint32_t qaddr = smem_u32(&Qs[wid * 16 + (lane & 15)][(lane >> 4) * 8]);
    const uint32_t kaddr = smem_u32(&Ks[(lane & 7) + ((lane >> 4) & 1) * 8]
                                       [((lane >> 3) & 1) * 8]);
    const uint32_t vaddr = smem_u32(&Vs[(lane & 7) + ((lane >> 3) & 1) * 8]
                                       [((lane >> 4) & 1) * 8]);

    const int ntiles = 2 * qb + 2;
    const int qrow0 = q0 + wid * 16 + g;
    const int wmax  = q0 + wid * 16 + 15;

    for (int t = 0; t < ntiles; t++) {
        const int kv0 = t * 64;
        __syncthreads();
        #pragma unroll
        for (int i = 0; i < 2; i++) {
            int idx = tid + i * 256;
            int r = idx >> 3, c8 = (idx & 7) * 8;
            *(uint4*)&Ks[r][c8] = *(const uint4*)(kbase + (size_t)(kv0 + r) * ld + c8);
            *(uint4*)&Vs[r][c8] = *(const uint4*)(vbase + (size_t)(kv0 + r) * ld + c8);
        }
        __syncthreads();

        if (kv0 > wmax) continue;

        float s[8][4];
        #pragma unroll
        for (int j = 0; j < 8; j++)
            #pragma unroll
            for (int r = 0; r < 4; r++) s[j][r] = 0.0f;
        #pragma unroll
        for (int kk = 0; kk < 4; kk++) {
            uint32_t qa[4];
            LDSM4(qa, qaddr + kk * 32);
            #pragma unroll
            for (int j2 = 0; j2 < 4; j2++) {
                uint32_t kb[4];
                LDSM4(kb, kaddr + j2 * (16 * AST * 2) + kk * 32);
                MMA16816(s[2 * j2],     qa, kb[0], kb[1]);
                MMA16816(s[2 * j2 + 1], qa, kb[2], kb[3]);
            }
        }

        const float scale = 0.125f;
        if (t >= ntiles - 2) {
            #pragma unroll
            for (int j = 0; j < 8; j++) {
                int col = kv0 + j * 8 + c2 * 2;
                s[j][0] = (col     > qrow0)     ? -1e30f : s[j][0] * scale;
                s[j][1] = (col + 1 > qrow0)     ? -1e30f : s[j][1] * scale;
                s[j][2] = (col     > qrow0 + 8) ? -1e30f : s[j][2] * scale;
                s[j][3] = (col + 1 > qrow0 + 8) ? -1e30f : s[j][3] * scale;
            }
        } else {
            #pragma unroll
            for (int j = 0; j < 8; j++)
                #pragma unroll
                for (int r = 0; r < 4; r++) s[j][r] *= scale;
        }

        float mx0 = -1e30f, mx1 = -1e30f;
        #pragma unroll
        for (int j = 0; j < 8; j++) {
            mx0 = fmaxf(mx0, fmaxf(s[j][0], s[j][1]));
            mx1 = fmaxf(mx1, fmaxf(s[j][2], s[j][3]));
        }
        mx0 = fmaxf(mx0, __shfl_xor_sync(0xffffffffu, mx0, 1));
        mx0 = fmaxf(mx0, __shfl_xor_sync(0xffffffffu, mx0, 2));
        mx1 = fmaxf(mx1, __shfl_xor_sync(0xffffffffu, mx1, 1));
        mx1 = fmaxf(mx1, __shfl_xor_sync(0xffffffffu, mx1, 2));
        float mn0 = fmaxf(mrow[0], mx0), mn1 = fmaxf(mrow[1], mx1);
        float fac0 = __expf(mrow[0] - mn0), fac1 = __expf(mrow[1] - mn1);
        float ps0 = 0.0f, ps1 = 0.0f;
        #pragma unroll
        for (int j = 0; j < 8; j++) {
            s[j][0] = __expf(s[j][0] - mn0);
            s[j][1] = __expf(s[j][1] - mn0);
            s[j][2] = __expf(s[j][2] - mn1);
            s[j][3] = __expf(s[j][3] - mn1);
            ps0 += s[j][0] + s[j][1];
            ps1 += s[j][2] + s[j][3];
        }
        ps0 += __shfl_xor_sync(0xffffffffu, ps0, 1);
        ps0 += __shfl_xor_sync(0xffffffffu, ps0, 2);
        ps1 += __shfl_xor_sync(0xffffffffu, ps1, 1);
        ps1 += __shfl_xor_sync(0xffffffffu, ps1, 2);
        lsum[0] = lsum[0] * fac0 + ps0;  mrow[0] = mn0;
        lsum[1] = lsum[1] * fac1 + ps1;  mrow[1] = mn1;
        #pragma unroll
        for (int j = 0; j < 8; j++) {
            o[j][0] *= fac0; o[j][1] *= fac0;
            o[j][2] *= fac1; o[j][3] *= fac1;
        }

        uint32_t pa[4][4];
        #pragma unroll
        for (int kk = 0; kk < 4; kk++) {
            pa[kk][0] = packh2(s[2 * kk][0],     s[2 * kk][1]);
            pa[kk][1] = packh2(s[2 * kk][2],     s[2 * kk][3]);
            pa[kk][2] = packh2(s[2 * kk + 1][0], s[2 * kk + 1][1]);
            pa[kk][3] = packh2(s[2 * kk + 1][2], s[2 * kk + 1][3]);
        }

        #pragma unroll
        for (int j2 = 0; j2 < 4; j2++) {
            #pragma unroll
            for (int kk = 0; kk < 4; kk++) {
                uint32_t vb[4];
                LDSM4T(vb, vaddr + kk * (16 * AST * 2) + j2 * 32);
                MMA16816(o[2 * j2],     pa[kk], vb[0], vb[1]);
                MMA16816(o[2 * j2 + 1], pa[kk], vb[2], vb[3]);
            }
        }
    }

    float inv0 = 1.0f / lsum[0], inv1 = 1.0f / lsum[1];
    const size_t rbase0 = ((size_t)(b * SEQ) + qrow0) * BDIM + hd * DHEAD;
    const size_t rbase1 = rbase0 + (size_t)8 * BDIM;
    #pragma unroll
    for (int j = 0; j < 8; j++) {
        int col = j * 8 + c2 * 2;
        *(__half2*)(outh + rbase0 + col) = __floats2half2_rn(o[j][0] * inv0, o[j][1] * inv0);
        *(__half2*)(outh + rbase1 + col) = __floats2half2_rn(o[j][2] * inv1, o[j][3] * inv1);
    }
}

// ===================== launch ==============================================
extern "C" void kernel_launch(void* const* d_in, const int* in_sizes, int n_in,
                              void* d_out, int out_size)
{
    const float* x      = (const float*)d_in[0];
    const float* w_qkv  = (const float*)d_in[1];
    const float* w_o    = (const float*)d_in[2];
    const float* w_up   = (const float*)d_in[3];
    const float* w_gate = (const float*)d_in[4];
    const float* w_down = (const float*)d_in[5];
    const float* scale1 = (const float*)d_in[6];
    const float* scale2 = (const float*)d_in[7];
    float* out = (float*)d_out;

    float *x1;
    __half *qkvh, *xnh, *ath, *hh;
    __half *wqkvh, *woh, *wuph, *wgh, *wdh;
    cudaGetSymbolAddress((void**)&x1,   g_x1);
    cudaGetSymbolAddress((void**)&qkvh, g_qkvh);
    cudaGetSymbolAddress((void**)&xnh, g_xnh);
    cudaGetSymbolAddress((void**)&ath, g_ath);
    cudaGetSymbolAddress((void**)&hh,  g_hh);
    cudaGetSymbolAddress((void**)&wqkvh, g_wqkvh);
    cudaGetSymbolAddress((void**)&woh, g_woh);
    cudaGetSymbolAddress((void**)&wuph, g_wuph);
    cudaGetSymbolAddress((void**)&wgh, g_wgh);
    cudaGetSymbolAddress((void**)&wdh, g_wdh);

    cudaFuncSetAttribute(gemm_hmma<1>,
                         cudaFuncAttributeMaxDynamicSharedMemorySize, GEMM_SMEM);
    cudaFuncSetAttribute(gemm_hmma<3>,
                         cudaFuncAttributeMaxDynamicSharedMemorySize, GEMM_SMEM);
    cudaFuncSetAttribute(gemm_upgate,
                         cudaFuncAttributeMaxDynamicSharedMemorySize, UG_SMEM);

    // 0. all weight converts in one launch
    cvt_all<<<(CV4 + 255) / 256, 256>>>(w_qkv, w_o, w_up, w_gate, w_down,
                                        wqkvh, woh, wuph, wgh, wdh);

    // 1. xn = rmsnorm(x, scale1) -> fp16
    rmsnorm_h<<<NTOK, 256>>>(x, scale1, xnh);

    // 2. qkvh = fp16(xn @ w_qkv.T)
    {
        dim3 g(3 * BDIM / BN, NTOK / BM);
        gemm_hmma<3><<<g, 256, GEMM_SMEM>>>(xnh, wqkvh, nullptr, nullptr, qkvh,
                                            NTOK, 3 * BDIM, BDIM);
    }

    // 3. attention core -> ath (fp16)
    {
        dim3 g(SEQ / 128, NHEAD, BATCH);
        flash_attn_h<<<g, 256>>>(qkvh, ath);
    }

    // 4. x1 = x + attn @ w_o.T
    {
        dim3 g(BDIM / BN, NTOK / BM);
        gemm_hmma<1><<<g, 256, GEMM_SMEM>>>(ath, woh, x1, x, nullptr,
                                            NTOK, BDIM, BDIM);
    }

    // 5. xn = rmsnorm(x1, scale2) -> fp16
    rmsnorm_h<<<NTOK, 256>>>(x1, scale2, xnh);

    // 6+7. hh = (xn @ w_up.T) * silu(xn @ w_gate.T)  (fused, fp16)
    {
        dim3 g(HID / BN, NTOK / BM);
        gemm_upgate<<<g, 256, UG_SMEM>>>(xnh, wuph, wgh, hh, NTOK, HID, BDIM);
    }

    // 8. out = x1 + hh @ w_down.T
    {
        dim3 g(BDIM / BN, NTOK / BM);
        gemm_hmma<1><<<g, 256, GEMM_SMEM>>>(hh, wdh, out, x1, nullptr,
                                            NTOK, BDIM, HID);
    }
}